// round 13
// baseline (speedup 1.0000x reference)
#include <cuda_runtime.h>
#include <cuda_bf16.h>
#include <math.h>
#include <stdint.h>

// Problem dims
#define BB 4
#define NN 1024
#define LL 1024
#define CC 1024
#define HH 16
#define DD 64
#define BH (BB*HH)          // 64
#define SCALE 0.125f        // D^-0.5
#define NEGV (-65504.0f)

// ---------------- scratch (device globals; no allocations allowed) ----------
__device__ float g_V[BB*HH*LL*DD];   // (B,H,L,D) fp32 (for V transpose)
__device__ int   g_maskflag;

// bf16 hi/lo buffers
__device__ __nv_bfloat16 g_qAh[BB*NN*CC], g_qAl[BB*NN*CC];      // query conv
__device__ __nv_bfloat16 g_mAh[BB*LL*CC], g_mAl[BB*LL*CC];      // memory conv
__device__ __nv_bfloat16 g_wQh[CC*CC],    g_wQl[CC*CC];         // q_w conv
__device__ __nv_bfloat16 g_wKVh[2*CC*CC], g_wKVl[2*CC*CC];      // kv_w conv
__device__ __nv_bfloat16 g_wPh[CC*CC],    g_wPl[CC*CC];         // proj_w conv
__device__ __nv_bfloat16 g_oAh[BB*NN*CC], g_oAl[BB*NN*CC];      // O packed (flash out)
__device__ __nv_bfloat16 g_cQh[BB*HH*NN*DD], g_cQl[BB*HH*NN*DD]; // Q scaled (bh,n,d)
__device__ __nv_bfloat16 g_cKh[BB*HH*LL*DD], g_cKl[BB*HH*LL*DD]; // K (bh,l,d)
__device__ uint32_t g_cVth[BB*HH*DD*LL/2], g_cVtl[BB*HH*DD*LL/2]; // V^T pair-packed

// ============================ helpers ========================================
__device__ __forceinline__ uint32_t smem_u32(const void* p) {
    uint32_t a;
    asm("{ .reg .u64 t; cvta.to.shared.u64 t, %1; cvt.u32.u64 %0, t; }" : "=r"(a) : "l"(p));
    return a;
}

__device__ __forceinline__ void cvt8(float4 x, float4 y, float s, uint4& h, uint4& l) {
    float a[8] = {x.x*s, x.y*s, x.z*s, x.w*s, y.x*s, y.y*s, y.z*s, y.w*s};
    unsigned int hh[4], ll[4];
#pragma unroll
    for (int i = 0; i < 4; i++) {
        __nv_bfloat16 h0 = __float2bfloat16(a[2*i]);
        __nv_bfloat16 h1 = __float2bfloat16(a[2*i+1]);
        float r0 = a[2*i]   - __bfloat162float(h0);
        float r1 = a[2*i+1] - __bfloat162float(h1);
        __nv_bfloat16 l0 = __float2bfloat16(r0);
        __nv_bfloat16 l1 = __float2bfloat16(r1);
        hh[i] = (unsigned)__bfloat16_as_ushort(h0) | ((unsigned)__bfloat16_as_ushort(h1) << 16);
        ll[i] = (unsigned)__bfloat16_as_ushort(l0) | ((unsigned)__bfloat16_as_ushort(l1) << 16);
    }
    h = make_uint4(hh[0], hh[1], hh[2], hh[3]);
    l = make_uint4(ll[0], ll[1], ll[2], ll[3]);
}

__device__ __forceinline__ uint32_t pack2bf(float x0, float x1, float& r0, float& r1) {
    __nv_bfloat16 h0 = __float2bfloat16(x0);
    __nv_bfloat16 h1 = __float2bfloat16(x1);
    r0 = x0 - __bfloat162float(h0);
    r1 = x1 - __bfloat162float(h1);
    return (unsigned)__bfloat16_as_ushort(h0) | ((unsigned)__bfloat16_as_ushort(h1) << 16);
}
__device__ __forceinline__ uint32_t pack2bf_only(float x0, float x1) {
    __nv_bfloat16 h0 = __float2bfloat16(x0);
    __nv_bfloat16 h1 = __float2bfloat16(x1);
    return (unsigned)__bfloat16_as_ushort(h0) | ((unsigned)__bfloat16_as_ushort(h1) << 16);
}

__device__ __forceinline__ void mma16816(float* c, uint32_t a0, uint32_t a1,
                                         uint32_t a2, uint32_t a3,
                                         uint32_t b0, uint32_t b1) {
    asm volatile(
        "mma.sync.aligned.m16n8k16.row.col.f32.bf16.bf16.f32 "
        "{%0,%1,%2,%3}, {%4,%5,%6,%7}, {%8,%9}, {%0,%1,%2,%3};"
        : "+f"(c[0]), "+f"(c[1]), "+f"(c[2]), "+f"(c[3])
        : "r"(a0), "r"(a1), "r"(a2), "r"(a3), "r"(b0), "r"(b1));
}

__device__ __forceinline__ void ldsm4(uint32_t* r, uint32_t addr) {
    asm volatile("ldmatrix.sync.aligned.m8n8.x4.shared.b16 {%0,%1,%2,%3}, [%4];"
        : "=r"(r[0]), "=r"(r[1]), "=r"(r[2]), "=r"(r[3]) : "r"(addr));
}

__device__ __forceinline__ void cp16(uint32_t saddr, const void* g) {
    asm volatile("cp.async.cg.shared.global [%0], [%1], 16;" :: "r"(saddr), "l"(g));
}
#define CP_COMMIT() asm volatile("cp.async.commit_group;" ::: "memory")
#define CP_WAIT2()  asm volatile("cp.async.wait_group 2;" ::: "memory")
#define CP_WAIT0()  asm volatile("cp.async.wait_group 0;" ::: "memory")

// ---------------- mask element-width detection ------------------------------
__global__ void detect_mask_kernel(const unsigned char* __restrict__ m) {
    __shared__ int s;
    if (threadIdx.x == 0) s = 0;
    __syncthreads();
    int found = 0;
    for (int j = threadIdx.x; j < 16384; j += 256)
        if (m[4*j + 1]) found = 1;
    if (found) atomicOr(&s, 1);
    __syncthreads();
    if (threadIdx.x == 0) g_maskflag = s;
}

// ---------------- all-input fp32 -> bf16 hi/lo conversion (one launch) ------
__global__ void __launch_bounds__(256)
conv_pre_kernel(const float* __restrict__ q, const float* __restrict__ m,
                const float* __restrict__ qw, const float* __restrict__ kvw,
                const float* __restrict__ pw) {
    int i = blockIdx.x * 256 + threadIdx.x;
    const float* src; uint4* oh; uint4* ol; int j;
    if (i < 524288)       { src = q;   oh = (uint4*)g_qAh;  ol = (uint4*)g_qAl;  j = i; }
    else if (i < 1048576) { src = m;   oh = (uint4*)g_mAh;  ol = (uint4*)g_mAl;  j = i - 524288; }
    else if (i < 1179648) { src = qw;  oh = (uint4*)g_wQh;  ol = (uint4*)g_wQl;  j = i - 1048576; }
    else if (i < 1441792) { src = kvw; oh = (uint4*)g_wKVh; ol = (uint4*)g_wKVl; j = i - 1179648; }
    else                  { src = pw;  oh = (uint4*)g_wPh;  ol = (uint4*)g_wPl;  j = i - 1441792; }
    float4 a = ((const float4*)src)[2*j];
    float4 b = ((const float4*)src)[2*j + 1];
    uint4 h, l;
    cvt8(a, b, 1.0f, h, l);
    oh[j] = h;
    ol[j] = l;
}

// ---------------- V transpose + hi/lo pack: g_V -> g_cVt{h,l} ---------------
__global__ void __launch_bounds__(256)
convVt_kernel() {
    __shared__ float tile[64][65];
    int bh = blockIdx.y, l0 = blockIdx.x * 64;
    int tid = threadIdx.x;
    const float* Vp = g_V + ((long)bh * LL + l0) * DD;
#pragma unroll
    for (int i = 0; i < 16; i++) {
        int idx = tid + 256 * i;
        int r = idx >> 6, d = idx & 63;
        tile[r][d] = Vp[(long)r * DD + d];
    }
    __syncthreads();
#pragma unroll
    for (int i = 0; i < 8; i++) {
        int w = tid + 256 * i;
        int d = w >> 5, j = w & 31;
        float v0 = tile[2*j][d], v1 = tile[2*j+1][d];
        float r0, r1;
        uint32_t hi = pack2bf(v0, v1, r0, r1);
        long o = ((long)bh * DD + d) * (LL/2) + (l0 >> 1) + j;
        g_cVth[o] = hi;
        g_cVtl[o] = pack2bf_only(r0, r1);
    }
}

// ====== pipelined bf16 GEMM core ============================================
#define GS_AH 0
#define GS_AL 8192
#define GS_BH 16384
#define GS_BL 24576
#define GS_STAGE 32768
#define G_SMEM_BYTES (3 * GS_STAGE)   // 98304

// combined Q + KV projection, flattened grid: x<8 -> Q tile x, else KV tile x-8
__global__ void __launch_bounds__(256, 2)
qkv_gemm_kernel() {
    int bx = blockIdx.x;
    int z = (bx < 8) ? 0 : 1;
    int nx = (bx < 8) ? bx : (bx - 8);
    const __nv_bfloat16 *Ah_, *Al_, *Bh_, *Bl_;
    if (z == 0) { Ah_ = g_qAh; Al_ = g_qAl; Bh_ = g_wQh;  Bl_ = g_wQl;  }
    else        { Ah_ = g_mAh; Al_ = g_mAl; Bh_ = g_wKVh; Bl_ = g_wKVl; }
    const int K = CC;

    extern __shared__ char smem[];
    uint32_t sbase = smem_u32(smem);
    int tid = threadIdx.x, lane = tid & 31, warp = tid >> 5;
    int m0 = blockIdx.y * 128, n0 = nx * 128;
    int wm = (warp >> 2) * 64, wn = (warp & 3) * 32;

    int row = tid >> 1, hs = tid & 1;
    int sw = (row >> 1) & 3;
    uint32_t off0 = (uint32_t)(row * 64 + (((2*hs)   ^ sw) << 4));
    uint32_t off1 = (uint32_t)(row * 64 + (((2*hs+1) ^ sw) << 4));
    const __nv_bfloat16* gAh = Ah_ + (long)(m0 + row) * K + hs * 16;
    const __nv_bfloat16* gAl = Al_ + (long)(m0 + row) * K + hs * 16;
    const __nv_bfloat16* gBh = Bh_ + (long)(n0 + row) * K + hs * 16;
    const __nv_bfloat16* gBl = Bl_ + (long)(n0 + row) * K + hs * 16;

    float acc[4][4][4];
#pragma unroll
    for (int i = 0; i < 4; i++)
#pragma unroll
        for (int j = 0; j < 4; j++)
#pragma unroll
            for (int q = 0; q < 4; q++) acc[i][j][q] = 0.f;

    const int nch = K >> 5;
    auto issue = [&](int stage, int k0) {
        uint32_t sb = sbase + stage * GS_STAGE;
        cp16(sb + GS_AH + off0, gAh + k0);
        cp16(sb + GS_AH + off1, gAh + k0 + 8);
        cp16(sb + GS_AL + off0, gAl + k0);
        cp16(sb + GS_AL + off1, gAl + k0 + 8);
        cp16(sb + GS_BH + off0, gBh + k0);
        cp16(sb + GS_BH + off1, gBh + k0 + 8);
        cp16(sb + GS_BL + off0, gBl + k0);
        cp16(sb + GS_BL + off1, gBl + k0 + 8);
    };

    int arow_l = (lane & 15);
    int akse   = (lane >> 4);
    int brow_l = ((lane >> 4) << 3) + (lane & 7);
    int bkse   = ((lane >> 3) & 1);

    issue(0, 0);  CP_COMMIT();
    issue(1, 32); CP_COMMIT();

    for (int c = 0; c < nch; c++) {
        if (c + 2 < nch) issue((c + 2) % 3, (c + 2) * 32);
        CP_COMMIT();
        CP_WAIT2();
        __syncthreads();

        uint32_t sb = sbase + (c % 3) * GS_STAGE;
#pragma unroll
        for (int ks = 0; ks < 2; ks++) {
            uint32_t a[4][4], bh[2][4], bl[2][4];
#pragma unroll
            for (int mf = 0; mf < 4; mf++) {
                int r = wm + mf * 16 + arow_l;
                int kg = ks * 2 + akse;
                ldsm4(a[mf], sb + GS_AH + r * 64 + ((kg ^ ((r >> 1) & 3)) << 4));
            }
#pragma unroll
            for (int np = 0; np < 2; np++) {
                int r = wn + np * 16 + brow_l;
                int kg = ks * 2 + bkse;
                uint32_t ro = (uint32_t)(r * 64 + ((kg ^ ((r >> 1) & 3)) << 4));
                ldsm4(bh[np], sb + GS_BH + ro);
                ldsm4(bl[np], sb + GS_BL + ro);
            }
#pragma unroll
            for (int mf = 0; mf < 4; mf++)
#pragma unroll
                for (int nf = 0; nf < 4; nf++) {
                    int np = nf >> 1, o = (nf & 1) * 2;
                    mma16816(acc[mf][nf], a[mf][0], a[mf][1], a[mf][2], a[mf][3],
                             bh[np][o], bh[np][o + 1]);
                }
#pragma unroll
            for (int mf = 0; mf < 4; mf++)
#pragma unroll
                for (int nf = 0; nf < 4; nf++) {
                    int np = nf >> 1, o = (nf & 1) * 2;
                    mma16816(acc[mf][nf], a[mf][0], a[mf][1], a[mf][2], a[mf][3],
                             bl[np][o], bl[np][o + 1]);
                }
#pragma unroll
            for (int mf = 0; mf < 4; mf++) {
                int r = wm + mf * 16 + arow_l;
                int kg = ks * 2 + akse;
                ldsm4(a[mf], sb + GS_AL + r * 64 + ((kg ^ ((r >> 1) & 3)) << 4));
            }
#pragma unroll
            for (int mf = 0; mf < 4; mf++)
#pragma unroll
                for (int nf = 0; nf < 4; nf++) {
                    int np = nf >> 1, o = (nf & 1) * 2;
                    mma16816(acc[mf][nf], a[mf][0], a[mf][1], a[mf][2], a[mf][3],
                             bh[np][o], bh[np][o + 1]);
                }
        }
        __syncthreads();
    }

#pragma unroll
    for (int mf = 0; mf < 4; mf++) {
        int m = m0 + wm + mf * 16 + (lane >> 2);
#pragma unroll
        for (int nf = 0; nf < 4; nf++) {
            int n = n0 + wn + nf * 8 + (lane & 3) * 2;
#pragma unroll
            for (int half = 0; half < 2; half++) {
                int mm = m + half * 8;
                float v0 = acc[mf][nf][2*half], v1 = acc[mf][nf][2*half + 1];
                int b = mm >> 10, rr = mm & 1023;
                if (z == 0) {
                    int hh = n >> 6, d = n & 63;
                    long e = (((long)(b << 4) + hh) * NN + rr) * DD + d;
                    float r0, r1;
                    uint32_t hi = pack2bf(v0 * SCALE, v1 * SCALE, r0, r1);
                    *(uint32_t*)&g_cQh[e] = hi;
                    *(uint32_t*)&g_cQl[e] = pack2bf_only(r0, r1);
                } else if (n < CC) {
                    int hh = n >> 6, d = n & 63;
                    long e = (((long)(b << 4) + hh) * LL + rr) * DD + d;
                    float r0, r1;
                    uint32_t hi = pack2bf(v0, v1, r0, r1);
                    *(uint32_t*)&g_cKh[e] = hi;
                    *(uint32_t*)&g_cKl[e] = pack2bf_only(r0, r1);
                } else {
                    int cc = n - CC, hh = cc >> 6, d = cc & 63;
                    *(float2*)&g_V[(((b << 4) + hh) * LL + rr) * DD + d] = make_float2(v0, v1);
                }
            }
        }
    }
}

// ---------------- output projection GEMM (reads packed O) -------------------
__global__ void __launch_bounds__(256, 2)
proj_gemm_kernel(float* __restrict__ out, const float* __restrict__ pb) {
    const __nv_bfloat16 *Ah_ = g_oAh, *Al_ = g_oAl, *Bh_ = g_wPh, *Bl_ = g_wPl;
    const int K = CC;

    extern __shared__ char smem[];
    uint32_t sbase = smem_u32(smem);
    int tid = threadIdx.x, lane = tid & 31, warp = tid >> 5;
    int m0 = blockIdx.y * 128, n0 = blockIdx.x * 128;
    int wm = (warp >> 2) * 64, wn = (warp & 3) * 32;

    int row = tid >> 1, hs = tid & 1;
    int sw = (row >> 1) & 3;
    uint32_t off0 = (uint32_t)(row * 64 + (((2*hs)   ^ sw) << 4));
    uint32_t off1 = (uint32_t)(row * 64 + (((2*hs+1) ^ sw) << 4));
    const __nv_bfloat16* gAh = Ah_ + (long)(m0 + row) * K + hs * 16;
    const __nv_bfloat16* gAl = Al_ + (long)(m0 + row) * K + hs * 16;
    const __nv_bfloat16* gBh = Bh_ + (long)(n0 + row) * K + hs * 16;
    const __nv_bfloat16* gBl = Bl_ + (long)(n0 + row) * K + hs * 16;

    float acc[4][4][4];
#pragma unroll
    for (int i = 0; i < 4; i++)
#pragma unroll
        for (int j = 0; j < 4; j++)
#pragma unroll
            for (int q = 0; q < 4; q++) acc[i][j][q] = 0.f;

    const int nch = K >> 5;
    auto issue = [&](int stage, int k0) {
        uint32_t sb = sbase + stage * GS_STAGE;
        cp16(sb + GS_AH + off0, gAh + k0);
        cp16(sb + GS_AH + off1, gAh + k0 + 8);
        cp16(sb + GS_AL + off0, gAl + k0);
        cp16(sb + GS_AL + off1, gAl + k0 + 8);
        cp16(sb + GS_BH + off0, gBh + k0);
        cp16(sb + GS_BH + off1, gBh + k0 + 8);
        cp16(sb + GS_BL + off0, gBl + k0);
        cp16(sb + GS_BL + off1, gBl + k0 + 8);
    };

    int arow_l = (lane & 15);
    int akse   = (lane >> 4);
    int brow_l = ((lane >> 4) << 3) + (lane & 7);
    int bkse   = ((lane >> 3) & 1);

    issue(0, 0);  CP_COMMIT();
    issue(1, 32); CP_COMMIT();

    for (int c = 0; c < nch; c++) {
        if (c + 2 < nch) issue((c + 2) % 3, (c + 2) * 32);
        CP_COMMIT();
        CP_WAIT2();
        __syncthreads();

        uint32_t sb = sbase + (c % 3) * GS_STAGE;
#pragma unroll
        for (int ks = 0; ks < 2; ks++) {
            uint32_t a[4][4], bh[2][4], bl[2][4];
#pragma unroll
            for (int mf = 0; mf < 4; mf++) {
                int r = wm + mf * 16 + arow_l;
                int kg = ks * 2 + akse;
                ldsm4(a[mf], sb + GS_AH + r * 64 + ((kg ^ ((r >> 1) & 3)) << 4));
            }
#pragma unroll
            for (int np = 0; np < 2; np++) {
                int r = wn + np * 16 + brow_l;
                int kg = ks * 2 + bkse;
                uint32_t ro = (uint32_t)(r * 64 + ((kg ^ ((r >> 1) & 3)) << 4));
                ldsm4(bh[np], sb + GS_BH + ro);
                ldsm4(bl[np], sb + GS_BL + ro);
            }
#pragma unroll
            for (int mf = 0; mf < 4; mf++)
#pragma unroll
                for (int nf = 0; nf < 4; nf++) {
                    int np = nf >> 1, o = (nf & 1) * 2;
                    mma16816(acc[mf][nf], a[mf][0], a[mf][1], a[mf][2], a[mf][3],
                             bh[np][o], bh[np][o + 1]);
                }
#pragma unroll
            for (int mf = 0; mf < 4; mf++)
#pragma unroll
                for (int nf = 0; nf < 4; nf++) {
                    int np = nf >> 1, o = (nf & 1) * 2;
                    mma16816(acc[mf][nf], a[mf][0], a[mf][1], a[mf][2], a[mf][3],
                             bl[np][o], bl[np][o + 1]);
                }
#pragma unroll
            for (int mf = 0; mf < 4; mf++) {
                int r = wm + mf * 16 + arow_l;
                int kg = ks * 2 + akse;
                ldsm4(a[mf], sb + GS_AL + r * 64 + ((kg ^ ((r >> 1) & 3)) << 4));
            }
#pragma unroll
            for (int mf = 0; mf < 4; mf++)
#pragma unroll
                for (int nf = 0; nf < 4; nf++) {
                    int np = nf >> 1, o = (nf & 1) * 2;
                    mma16816(acc[mf][nf], a[mf][0], a[mf][1], a[mf][2], a[mf][3],
                             bh[np][o], bh[np][o + 1]);
                }
        }
        __syncthreads();
    }

#pragma unroll
    for (int mf = 0; mf < 4; mf++) {
        int m = m0 + wm + mf * 16 + (lane >> 2);
#pragma unroll
        for (int nf = 0; nf < 4; nf++) {
            int n = n0 + wn + nf * 8 + (lane & 3) * 2;
            float2 bb = *(const float2*)&pb[n];
            *(float2*)&out[(long)m * CC + n] =
                make_float2(acc[mf][nf][0] + bb.x, acc[mf][nf][1] + bb.y);
            *(float2*)&out[(long)(m + 8) * CC + n] =
                make_float2(acc[mf][nf][2] + bb.x, acc[mf][nf][3] + bb.y);
        }
    }
}

// ===== fused flash attention (R13: Q in registers, 3-stage KV pipeline) =====
// smem: 3 stages x 36864B: Kh[4608h] Kl[4608h] Vh[4608h] Vl[4608h]
#define FA_STAGE_B 36864u
#define FA_SMEM_BYTES (3 * 36864)   // 110592

__global__ void __launch_bounds__(256, 2)
flash_attn_kernel(const float* __restrict__ bias,
                  const unsigned char* __restrict__ mask8,
                  float* __restrict__ attn) {
    extern __shared__ __nv_bfloat16 fsm[];
    uint32_t fb = smem_u32(fsm);

    int bh = blockIdx.y, m0 = blockIdx.x * 128;
    int b = bh >> 4, h = bh & 15;
    int tid = threadIdx.x, lane = tid & 31, w = tid >> 5;
    int g = lane >> 2, t = lane & 3;

    // K/V producers: 4 threads per row
    int pr = tid >> 2, ps = (tid & 3) * 2;

    auto issueKV = [&](int s, int lc) {
        uint32_t sb = fb + (uint32_t)s * FA_STAGE_B;
        const __nv_bfloat16* kh = &g_cKh[((long)bh * LL + lc * 64 + pr) * DD + ps * 8];
        const __nv_bfloat16* kl = &g_cKl[((long)bh * LL + lc * 64 + pr) * DD + ps * 8];
#pragma unroll
        for (int i = 0; i < 2; i++) {
            cp16(sb + pr * 144 + (ps + i) * 16, kh + i * 8);
            cp16(sb + 9216u + pr * 144 + (ps + i) * 16, kl + i * 8);
        }
        const uint32_t* vh = &g_cVth[((long)bh * DD + pr) * (LL/2) + lc * 32 + ps * 4];
        const uint32_t* vl = &g_cVtl[((long)bh * DD + pr) * (LL/2) + lc * 32 + ps * 4];
#pragma unroll
        for (int i = 0; i < 2; i++) {
            cp16(sb + 18432u + pr * 144 + (ps + i) * 16, vh + i * 4);
            cp16(sb + 27648u + pr * 144 + (ps + i) * 16, vl + i * 4);
        }
    };

    issueKV(0, 0); CP_COMMIT();
    issueKV(1, 1); CP_COMMIT();

    // ---- Q fragments loaded directly into registers (A-frag layout) ----
    uint32_t qfh[4][4], qfl[4][4];
    {
        long qo = ((long)bh * NN + m0 + 16 * w + (lane >> 2)) * DD + 2 * (lane & 3);
        const __nv_bfloat16* qbh = g_cQh + qo;
        const __nv_bfloat16* qbl = g_cQl + qo;
#pragma unroll
        for (int ks = 0; ks < 4; ks++) {
            qfh[ks][0] = *(const uint32_t*)(qbh + ks * 16);
            qfh[ks][1] = *(const uint32_t*)(qbh + ks * 16 + 8 * DD);
            qfh[ks][2] = *(const uint32_t*)(qbh + ks * 16 + 8);
            qfh[ks][3] = *(const uint32_t*)(qbh + ks * 16 + 8 * DD + 8);
            qfl[ks][0] = *(const uint32_t*)(qbl + ks * 16);
            qfl[ks][1] = *(const uint32_t*)(qbl + ks * 16 + 8 * DD);
            qfl[ks][2] = *(const uint32_t*)(qbl + ks * 16 + 8);
            qfl[ks][3] = *(const uint32_t*)(qbl + ks * 16 + 8 * DD + 8);
        }
    }

    float om0 = -1e30f, os0 = 0.f, om1 = -1e30f, os1 = 0.f;
    float acco[8][4];
#pragma unroll
    for (int i = 0; i < 8; i++)
#pragma unroll
        for (int q = 0; q < 4; q++) acco[i][q] = 0.f;

    const int arow = 16 * w + g;
    const int flag = g_maskflag;

    // B-frag lane addressing (same proven mapping as gemm kernels)
    const uint32_t b_r  = (uint32_t)(((lane >> 4) << 3) + (lane & 7));
    const uint32_t b_kg = (uint32_t)((lane >> 3) & 1);

    for (int lc = 0; lc < 16; lc++) {
        if (lc + 2 < 16) issueKV((lc + 2) % 3, lc + 2);
        CP_COMMIT();
        CP_WAIT2();
        __syncthreads();

        uint32_t stb = fb + (uint32_t)(lc % 3) * FA_STAGE_B;
        uint32_t Khb = stb, Klb = stb + 9216u, Vhb = stb + 18432u, Vlb = stb + 27648u;

        float sacc[8][4];
#pragma unroll
        for (int i = 0; i < 8; i++)
#pragma unroll
            for (int q = 0; q < 4; q++) sacc[i][q] = 0.f;

#pragma unroll
        for (int ks = 0; ks < 4; ks++) {
            uint32_t kg = ks * 2u + b_kg;
#pragma unroll
            for (int np = 0; np < 4; np++) {
                uint32_t kh[4], kl[4];
                uint32_t ro = (np * 16u + b_r) * 144u + kg * 16u;
                ldsm4(kh, Khb + ro);
                ldsm4(kl, Klb + ro);
#pragma unroll
                for (int j = 0; j < 2; j++) {
                    int nf = 2 * np + j, o = j * 2;
                    mma16816(sacc[nf], qfh[ks][0], qfh[ks][1], qfh[ks][2], qfh[ks][3], kh[o], kh[o+1]);
                    mma16816(sacc[nf], qfl[ks][0], qfl[ks][1], qfl[ks][2], qfl[ks][3], kh[o], kh[o+1]);
                    mma16816(sacc[nf], qfh[ks][0], qfh[ks][1], qfh[ks][2], qfh[ks][3], kl[o], kl[o+1]);
                }
            }
        }

        // mask + bias, write attn_wo_softmax
        int r0g = m0 + arow;
        long rb0 = ((long)bh * NN + r0g) * LL + lc * 64;
        long rb1 = rb0 + 8 * LL;
        long rm0 = ((long)b * NN + r0g) * LL + lc * 64;
        long rm1 = rm0 + 8 * LL;
#pragma unroll
        for (int nf = 0; nf < 8; nf++) {
            int col = nf * 8 + 2 * t;
            float v0 = sacc[nf][0], v1 = sacc[nf][1];
            float v2 = sacc[nf][2], v3 = sacc[nf][3];
            if (flag) {
                unsigned short mA = *(const unsigned short*)&mask8[rm0 + col];
                unsigned short mB = *(const unsigned short*)&mask8[rm1 + col];
                if (mA & 0x00ff) v0 = NEGV;
                if (mA & 0xff00) v1 = NEGV;
                if (mB & 0x00ff) v2 = NEGV;
                if (mB & 0xff00) v3 = NEGV;
            } else {
                const unsigned int* m32 = (const unsigned int*)mask8;
                uint2 mA = *(const uint2*)&m32[rm0 + col];
                uint2 mB = *(const uint2*)&m32[rm1 + col];
                if (mA.x) v0 = NEGV;
                if (mA.y) v1 = NEGV;
                if (mB.x) v2 = NEGV;
                if (mB.y) v3 = NEGV;
            }
            float2 bb0 = *(const float2*)&bias[rb0 + col];
            float2 bb1 = *(const float2*)&bias[rb1 + col];
            v0 += bb0.x; v1 += bb0.y; v2 += bb1.x; v3 += bb1.y;
            *(float2*)&attn[rb0 + col] = make_float2(v0, v1);
            *(float2*)&attn[rb1 + col] = make_float2(v2, v3);
            sacc[nf][0] = v0; sacc[nf][1] = v1; sacc[nf][2] = v2; sacc[nf][3] = v3;
        }

        // online softmax (exp in place)
        float cm0 = -1e30f, cm1 = -1e30f;
#pragma unroll
        for (int nf = 0; nf < 8; nf++) {
            cm0 = fmaxf(cm0, fmaxf(sacc[nf][0], sacc[nf][1]));
            cm1 = fmaxf(cm1, fmaxf(sacc[nf][2], sacc[nf][3]));
        }
        cm0 = fmaxf(cm0, __shfl_xor_sync(0xffffffffu, cm0, 1));
        cm0 = fmaxf(cm0, __shfl_xor_sync(0xffffffffu, cm0, 2));
        cm1 = fmaxf(cm1, __shfl_xor_sync(0xffffffffu, cm1, 1));
        cm1 = fmaxf(cm1, __shfl_xor_sync(0xffffffffu, cm1, 2));
        float mn0 = fmaxf(om0, cm0), mn1 = fmaxf(om1, cm1);

        float cs0 = 0.f, cs1 = 0.f;
#pragma unroll
        for (int nf = 0; nf < 8; nf++) {
            float p0 = __expf(sacc[nf][0] - mn0);
            float p1 = __expf(sacc[nf][1] - mn0);
            float p2 = __expf(sacc[nf][2] - mn1);
            float p3 = __expf(sacc[nf][3] - mn1);
            cs0 += p0 + p1; cs1 += p2 + p3;
            sacc[nf][0] = p0; sacc[nf][1] = p1;
            sacc[nf][2] = p2; sacc[nf][3] = p3;
        }
        cs0 += __shfl_xor_sync(0xffffffffu, cs0, 1);
        cs0 += __shfl_xor_sync(0xffffffffu, cs0, 2);
        cs1 += __shfl_xor_sync(0xffffffffu, cs1, 1);
        cs1 += __shfl_xor_sync(0xffffffffu, cs1, 2);
        float f0 = __expf(om0 - mn0), f1 = __expf(om1 - mn1);
        os0 = os0 * f0 + cs0; os1 = os1 * f1 + cs1;
        om0 = mn0; om1 = mn1;

#pragma unroll
        for (int nb = 0; nb < 8; nb++) {
            acco[nb][0] *= f0; acco[nb][1] *= f0;
            acco[nb][2] *= f1; acco[nb][3] *= f1;
        }

        // O += P @ V (3-pass hi/lo), P packed on the fly, V frags via ldmatrix
#pragma unroll
        for (int ks = 0; ks < 4; ks++) {
            float e0, e1, e2, e3, e4, e5, e6, e7;
            uint32_t pa0 = pack2bf(sacc[2*ks][0],   sacc[2*ks][1],   e0, e1);
            uint32_t pa1 = pack2bf(sacc[2*ks][2],   sacc[2*ks][3],   e2, e3);
            uint32_t pa2 = pack2bf(sacc[2*ks+1][0], sacc[2*ks+1][1], e4, e5);
            uint32_t pa3 = pack2bf(sacc[2*ks+1][2], sacc[2*ks+1][3], e6, e7);
            uint32_t qa0 = pack2bf_only(e0, e1);
            uint32_t qa1 = pack2bf_only(e2, e3);
            uint32_t qa2 = pack2bf_only(e4, e5);
            uint32_t qa3 = pack2bf_only(e6, e7);
            uint32_t kg = ks * 2u + b_kg;
#pragma unroll
            for (int np = 0; np < 4; np++) {
                uint32_t vh[4], vl[4];
                uint32_t ro = (np * 16u + b_r) * 144u + kg * 16u;
                ldsm4(vh, Vhb + ro);
                ldsm4(vl, Vlb + ro);
#pragma unroll
                for (int j = 0; j < 2; j++) {
                    int nb = 2 * np + j, o = j * 2;
                    mma16816(acco[nb], pa0, pa1, pa2, pa3, vh[o], vh[o+1]);
                    mma16816(acco[nb], qa0, qa1, qa2, qa3, vh[o], vh[o+1]);
                    mma16816(acco[nb], pa0, pa1, pa2, pa3, vl[o], vl[o+1]);
                }
            }
        }
        __syncthreads();
    }

    // O epilogue: write packed bf16 hi/lo directly (layout = proj A operand)
    float rv0 = 1.0f / os0, rv1 = 1.0f / os1;
    int r0g = m0 + arow;
    uint32_t* oh = (uint32_t*)g_oAh;
    uint32_t* ol = (uint32_t*)g_oAl;
    long ob0w = (((long)b * NN + r0g) * CC + h * 64) >> 1;
    long ob1w = (((long)b * NN + r0g + 8) * CC + h * 64) >> 1;
#pragma unroll
    for (int nb = 0; nb < 8; nb++) {
        int dw = nb * 4 + t;
        float r0, r1;
        uint32_t hi0 = pack2bf(acco[nb][0] * rv0, acco[nb][1] * rv0, r0, r1);
        oh[ob0w + dw] = hi0;
        ol[ob0w + dw] = pack2bf_only(r0, r1);
        uint32_t hi1 = pack2bf(acco[nb][2] * rv1, acco[nb][3] * rv1, r0, r1);
        oh[ob1w + dw] = hi1;
        ol[ob1w + dw] = pack2bf_only(r0, r1);
    }
}

// ---------------- launch --------------------------------------------------
extern "C" void kernel_launch(void* const* d_in, const int* in_sizes, int n_in,
                              void* d_out, int out_size) {
    const float* query  = (const float*)d_in[0];
    const float* memory = (const float*)d_in[1];
    const float* bias   = (const float*)d_in[2];
    const unsigned char* mask = (const unsigned char*)d_in[3];
    const float* q_w    = (const float*)d_in[4];
    const float* kv_w   = (const float*)d_in[5];
    const float* proj_w = (const float*)d_in[6];
    const float* proj_b = (const float*)d_in[7];

    float* x_out    = (float*)d_out;
    float* attn_out = x_out + (long)BB * NN * CC;   // x first, then attn_wo_softmax

    (void)in_sizes; (void)n_in; (void)out_size;

    static int inited = 0;
    if (!inited) {
        cudaFuncSetAttribute(qkv_gemm_kernel,  cudaFuncAttributeMaxDynamicSharedMemorySize, G_SMEM_BYTES);
        cudaFuncSetAttribute(proj_gemm_kernel, cudaFuncAttributeMaxDynamicSharedMemorySize, G_SMEM_BYTES);
        cudaFuncSetAttribute(flash_attn_kernel, cudaFuncAttributeMaxDynamicSharedMemorySize, FA_SMEM_BYTES);
        inited = 1;
    }

    detect_mask_kernel<<<1, 256>>>(mask);

    // all input conversions in one launch
    conv_pre_kernel<<<6144, 256>>>(query, memory, q_w, kv_w, proj_w);

    // Q + KV projections, flattened grid (no dead CTAs)
    qkv_gemm_kernel<<<dim3(24, 32), 256, G_SMEM_BYTES>>>();

    // V transpose to pair-packed bf16 hi/lo
    convVt_kernel<<<dim3(LL/64, BH), 256>>>();

    // fused attention: S (+mask+bias) -> attn_out, online softmax, packed O
    flash_attn_kernel<<<dim3(NN/128, BH), 256, FA_SMEM_BYTES>>>(bias, mask, attn_out);

    // output projection
    proj_gemm_kernel<<<dim3(CC/128, (BB*NN)/128), 256, G_SMEM_BYTES>>>(x_out, proj_b);
}

// round 14
// speedup vs baseline: 1.0327x; 1.0327x over previous
#include <cuda_runtime.h>
#include <cuda_bf16.h>
#include <math.h>
#include <stdint.h>

// Problem dims
#define BB 4
#define NN 1024
#define LL 1024
#define CC 1024
#define HH 16
#define DD 64
#define BH (BB*HH)          // 64
#define SCALE 0.125f        // D^-0.5
#define NEGV (-65504.0f)

// ---------------- scratch (device globals; no allocations allowed) ----------
__device__ float g_V[BB*HH*LL*DD];   // (B,H,L,D) fp32 (for V transpose)
__device__ int   g_maskflag;

// bf16 hi/lo buffers
__device__ __nv_bfloat16 g_qAh[BB*NN*CC], g_qAl[BB*NN*CC];      // query conv
__device__ __nv_bfloat16 g_mAh[BB*LL*CC], g_mAl[BB*LL*CC];      // memory conv
__device__ __nv_bfloat16 g_wQh[CC*CC],    g_wQl[CC*CC];         // q_w conv
__device__ __nv_bfloat16 g_wKVh[2*CC*CC], g_wKVl[2*CC*CC];      // kv_w conv
__device__ __nv_bfloat16 g_wPh[CC*CC],    g_wPl[CC*CC];         // proj_w conv
__device__ __nv_bfloat16 g_oAh[BB*NN*CC], g_oAl[BB*NN*CC];      // O packed (flash out)
__device__ __nv_bfloat16 g_cQh[BB*HH*NN*DD], g_cQl[BB*HH*NN*DD]; // Q scaled (bh,n,d)
__device__ __nv_bfloat16 g_cKh[BB*HH*LL*DD], g_cKl[BB*HH*LL*DD]; // K (bh,l,d)
__device__ uint32_t g_cVth[BB*HH*DD*LL/2], g_cVtl[BB*HH*DD*LL/2]; // V^T pair-packed

// ============================ helpers ========================================
__device__ __forceinline__ uint32_t smem_u32(const void* p) {
    uint32_t a;
    asm("{ .reg .u64 t; cvta.to.shared.u64 t, %1; cvt.u32.u64 %0, t; }" : "=r"(a) : "l"(p));
    return a;
}

__device__ __forceinline__ void cvt8(float4 x, float4 y, float s, uint4& h, uint4& l) {
    float a[8] = {x.x*s, x.y*s, x.z*s, x.w*s, y.x*s, y.y*s, y.z*s, y.w*s};
    unsigned int hh[4], ll[4];
#pragma unroll
    for (int i = 0; i < 4; i++) {
        __nv_bfloat16 h0 = __float2bfloat16(a[2*i]);
        __nv_bfloat16 h1 = __float2bfloat16(a[2*i+1]);
        float r0 = a[2*i]   - __bfloat162float(h0);
        float r1 = a[2*i+1] - __bfloat162float(h1);
        __nv_bfloat16 l0 = __float2bfloat16(r0);
        __nv_bfloat16 l1 = __float2bfloat16(r1);
        hh[i] = (unsigned)__bfloat16_as_ushort(h0) | ((unsigned)__bfloat16_as_ushort(h1) << 16);
        ll[i] = (unsigned)__bfloat16_as_ushort(l0) | ((unsigned)__bfloat16_as_ushort(l1) << 16);
    }
    h = make_uint4(hh[0], hh[1], hh[2], hh[3]);
    l = make_uint4(ll[0], ll[1], ll[2], ll[3]);
}

__device__ __forceinline__ uint32_t pack2bf(float x0, float x1, float& r0, float& r1) {
    __nv_bfloat16 h0 = __float2bfloat16(x0);
    __nv_bfloat16 h1 = __float2bfloat16(x1);
    r0 = x0 - __bfloat162float(h0);
    r1 = x1 - __bfloat162float(h1);
    return (unsigned)__bfloat16_as_ushort(h0) | ((unsigned)__bfloat16_as_ushort(h1) << 16);
}
__device__ __forceinline__ uint32_t pack2bf_only(float x0, float x1) {
    __nv_bfloat16 h0 = __float2bfloat16(x0);
    __nv_bfloat16 h1 = __float2bfloat16(x1);
    return (unsigned)__bfloat16_as_ushort(h0) | ((unsigned)__bfloat16_as_ushort(h1) << 16);
}

__device__ __forceinline__ void mma16816(float* c, uint32_t a0, uint32_t a1,
                                         uint32_t a2, uint32_t a3,
                                         uint32_t b0, uint32_t b1) {
    asm volatile(
        "mma.sync.aligned.m16n8k16.row.col.f32.bf16.bf16.f32 "
        "{%0,%1,%2,%3}, {%4,%5,%6,%7}, {%8,%9}, {%0,%1,%2,%3};"
        : "+f"(c[0]), "+f"(c[1]), "+f"(c[2]), "+f"(c[3])
        : "r"(a0), "r"(a1), "r"(a2), "r"(a3), "r"(b0), "r"(b1));
}

__device__ __forceinline__ void ldsm4(uint32_t* r, uint32_t addr) {
    asm volatile("ldmatrix.sync.aligned.m8n8.x4.shared.b16 {%0,%1,%2,%3}, [%4];"
        : "=r"(r[0]), "=r"(r[1]), "=r"(r[2]), "=r"(r[3]) : "r"(addr));
}

__device__ __forceinline__ void cp16(uint32_t saddr, const void* g) {
    asm volatile("cp.async.cg.shared.global [%0], [%1], 16;" :: "r"(saddr), "l"(g));
}
#define CP_COMMIT() asm volatile("cp.async.commit_group;" ::: "memory")
#define CP_WAIT2()  asm volatile("cp.async.wait_group 2;" ::: "memory")
#define CP_WAIT1()  asm volatile("cp.async.wait_group 1;" ::: "memory")
#define CP_WAIT0()  asm volatile("cp.async.wait_group 0;" ::: "memory")

// ------- all-input fp32 -> bf16 hi/lo conversion + mask detect (one launch) -
__global__ void __launch_bounds__(256)
conv_pre_kernel(const float* __restrict__ q, const float* __restrict__ m,
                const float* __restrict__ qw, const float* __restrict__ kvw,
                const float* __restrict__ pw, const unsigned char* __restrict__ mk) {
    if (blockIdx.x == 6144) {
        // mask element-width detection (see R0 note: byte (4k+1) is 0 for 4-byte storage)
        __shared__ int s;
        if (threadIdx.x == 0) s = 0;
        __syncthreads();
        int found = 0;
        for (int j = threadIdx.x; j < 16384; j += 256)
            if (mk[4*j + 1]) found = 1;
        if (found) atomicOr(&s, 1);
        __syncthreads();
        if (threadIdx.x == 0) g_maskflag = s;
        return;
    }
    int i = blockIdx.x * 256 + threadIdx.x;
    const float* src; uint4* oh; uint4* ol; int j;
    if (i < 524288)       { src = q;   oh = (uint4*)g_qAh;  ol = (uint4*)g_qAl;  j = i; }
    else if (i < 1048576) { src = m;   oh = (uint4*)g_mAh;  ol = (uint4*)g_mAl;  j = i - 524288; }
    else if (i < 1179648) { src = qw;  oh = (uint4*)g_wQh;  ol = (uint4*)g_wQl;  j = i - 1048576; }
    else if (i < 1441792) { src = kvw; oh = (uint4*)g_wKVh; ol = (uint4*)g_wKVl; j = i - 1179648; }
    else                  { src = pw;  oh = (uint4*)g_wPh;  ol = (uint4*)g_wPl;  j = i - 1441792; }
    float4 a = ((const float4*)src)[2*j];
    float4 b = ((const float4*)src)[2*j + 1];
    uint4 h, l;
    cvt8(a, b, 1.0f, h, l);
    oh[j] = h;
    ol[j] = l;
}

// ---------------- V transpose + hi/lo pack: g_V -> g_cVt{h,l} ---------------
__global__ void __launch_bounds__(256)
convVt_kernel() {
    __shared__ float tile[64][65];
    int bh = blockIdx.y, l0 = blockIdx.x * 64;
    int tid = threadIdx.x;
    const float* Vp = g_V + ((long)bh * LL + l0) * DD;
#pragma unroll
    for (int i = 0; i < 16; i++) {
        int idx = tid + 256 * i;
        int r = idx >> 6, d = idx & 63;
        tile[r][d] = Vp[(long)r * DD + d];
    }
    __syncthreads();
#pragma unroll
    for (int i = 0; i < 8; i++) {
        int w = tid + 256 * i;
        int d = w >> 5, j = w & 31;
        float v0 = tile[2*j][d], v1 = tile[2*j+1][d];
        float r0, r1;
        uint32_t hi = pack2bf(v0, v1, r0, r1);
        long o = ((long)bh * DD + d) * (LL/2) + (l0 >> 1) + j;
        g_cVth[o] = hi;
        g_cVtl[o] = pack2bf_only(r0, r1);
    }
}

// ====== pipelined bf16 GEMM core ============================================
#define GS_AH 0
#define GS_AL 8192
#define GS_BH 16384
#define GS_BL 24576
#define GS_STAGE 32768
#define G_SMEM_BYTES (3 * GS_STAGE)   // 98304

// combined Q + KV projection, flattened grid: x<8 -> Q tile x, else KV tile x-8
__global__ void __launch_bounds__(256, 2)
qkv_gemm_kernel() {
    int bx = blockIdx.x;
    int z = (bx < 8) ? 0 : 1;
    int nx = (bx < 8) ? bx : (bx - 8);
    const __nv_bfloat16 *Ah_, *Al_, *Bh_, *Bl_;
    if (z == 0) { Ah_ = g_qAh; Al_ = g_qAl; Bh_ = g_wQh;  Bl_ = g_wQl;  }
    else        { Ah_ = g_mAh; Al_ = g_mAl; Bh_ = g_wKVh; Bl_ = g_wKVl; }
    const int K = CC;

    extern __shared__ char smem[];
    uint32_t sbase = smem_u32(smem);
    int tid = threadIdx.x, lane = tid & 31, warp = tid >> 5;
    int m0 = blockIdx.y * 128, n0 = nx * 128;
    int wm = (warp >> 2) * 64, wn = (warp & 3) * 32;

    int row = tid >> 1, hs = tid & 1;
    int sw = (row >> 1) & 3;
    uint32_t off0 = (uint32_t)(row * 64 + (((2*hs)   ^ sw) << 4));
    uint32_t off1 = (uint32_t)(row * 64 + (((2*hs+1) ^ sw) << 4));
    const __nv_bfloat16* gAh = Ah_ + (long)(m0 + row) * K + hs * 16;
    const __nv_bfloat16* gAl = Al_ + (long)(m0 + row) * K + hs * 16;
    const __nv_bfloat16* gBh = Bh_ + (long)(n0 + row) * K + hs * 16;
    const __nv_bfloat16* gBl = Bl_ + (long)(n0 + row) * K + hs * 16;

    float acc[4][4][4];
#pragma unroll
    for (int i = 0; i < 4; i++)
#pragma unroll
        for (int j = 0; j < 4; j++)
#pragma unroll
            for (int q = 0; q < 4; q++) acc[i][j][q] = 0.f;

    const int nch = K >> 5;
    auto issue = [&](int stage, int k0) {
        uint32_t sb = sbase + stage * GS_STAGE;
        cp16(sb + GS_AH + off0, gAh + k0);
        cp16(sb + GS_AH + off1, gAh + k0 + 8);
        cp16(sb + GS_AL + off0, gAl + k0);
        cp16(sb + GS_AL + off1, gAl + k0 + 8);
        cp16(sb + GS_BH + off0, gBh + k0);
        cp16(sb + GS_BH + off1, gBh + k0 + 8);
        cp16(sb + GS_BL + off0, gBl + k0);
        cp16(sb + GS_BL + off1, gBl + k0 + 8);
    };

    int arow_l = (lane & 15);
    int akse   = (lane >> 4);
    int brow_l = ((lane >> 4) << 3) + (lane & 7);
    int bkse   = ((lane >> 3) & 1);

    issue(0, 0);  CP_COMMIT();
    issue(1, 32); CP_COMMIT();

    for (int c = 0; c < nch; c++) {
        if (c + 2 < nch) issue((c + 2) % 3, (c + 2) * 32);
        CP_COMMIT();
        CP_WAIT2();
        __syncthreads();

        uint32_t sb = sbase + (c % 3) * GS_STAGE;
#pragma unroll
        for (int ks = 0; ks < 2; ks++) {
            uint32_t a[4][4], bh[2][4], bl[2][4];
#pragma unroll
            for (int mf = 0; mf < 4; mf++) {
                int r = wm + mf * 16 + arow_l;
                int kg = ks * 2 + akse;
                ldsm4(a[mf], sb + GS_AH + r * 64 + ((kg ^ ((r >> 1) & 3)) << 4));
            }
#pragma unroll
            for (int np = 0; np < 2; np++) {
                int r = wn + np * 16 + brow_l;
                int kg = ks * 2 + bkse;
                uint32_t ro = (uint32_t)(r * 64 + ((kg ^ ((r >> 1) & 3)) << 4));
                ldsm4(bh[np], sb + GS_BH + ro);
                ldsm4(bl[np], sb + GS_BL + ro);
            }
#pragma unroll
            for (int mf = 0; mf < 4; mf++)
#pragma unroll
                for (int nf = 0; nf < 4; nf++) {
                    int np = nf >> 1, o = (nf & 1) * 2;
                    mma16816(acc[mf][nf], a[mf][0], a[mf][1], a[mf][2], a[mf][3],
                             bh[np][o], bh[np][o + 1]);
                }
#pragma unroll
            for (int mf = 0; mf < 4; mf++)
#pragma unroll
                for (int nf = 0; nf < 4; nf++) {
                    int np = nf >> 1, o = (nf & 1) * 2;
                    mma16816(acc[mf][nf], a[mf][0], a[mf][1], a[mf][2], a[mf][3],
                             bl[np][o], bl[np][o + 1]);
                }
#pragma unroll
            for (int mf = 0; mf < 4; mf++) {
                int r = wm + mf * 16 + arow_l;
                int kg = ks * 2 + akse;
                ldsm4(a[mf], sb + GS_AL + r * 64 + ((kg ^ ((r >> 1) & 3)) << 4));
            }
#pragma unroll
            for (int mf = 0; mf < 4; mf++)
#pragma unroll
                for (int nf = 0; nf < 4; nf++) {
                    int np = nf >> 1, o = (nf & 1) * 2;
                    mma16816(acc[mf][nf], a[mf][0], a[mf][1], a[mf][2], a[mf][3],
                             bh[np][o], bh[np][o + 1]);
                }
        }
        __syncthreads();
    }

#pragma unroll
    for (int mf = 0; mf < 4; mf++) {
        int m = m0 + wm + mf * 16 + (lane >> 2);
#pragma unroll
        for (int nf = 0; nf < 4; nf++) {
            int n = n0 + wn + nf * 8 + (lane & 3) * 2;
#pragma unroll
            for (int half = 0; half < 2; half++) {
                int mm = m + half * 8;
                float v0 = acc[mf][nf][2*half], v1 = acc[mf][nf][2*half + 1];
                int b = mm >> 10, rr = mm & 1023;
                if (z == 0) {
                    int hh = n >> 6, d = n & 63;
                    long e = (((long)(b << 4) + hh) * NN + rr) * DD + d;
                    float r0, r1;
                    uint32_t hi = pack2bf(v0 * SCALE, v1 * SCALE, r0, r1);
                    *(uint32_t*)&g_cQh[e] = hi;
                    *(uint32_t*)&g_cQl[e] = pack2bf_only(r0, r1);
                } else if (n < CC) {
                    int hh = n >> 6, d = n & 63;
                    long e = (((long)(b << 4) + hh) * LL + rr) * DD + d;
                    float r0, r1;
                    uint32_t hi = pack2bf(v0, v1, r0, r1);
                    *(uint32_t*)&g_cKh[e] = hi;
                    *(uint32_t*)&g_cKl[e] = pack2bf_only(r0, r1);
                } else {
                    int cc = n - CC, hh = cc >> 6, d = cc & 63;
                    *(float2*)&g_V[(((b << 4) + hh) * LL + rr) * DD + d] = make_float2(v0, v1);
                }
            }
        }
    }
}

// ---------------- output projection GEMM (reads packed O) -------------------
__global__ void __launch_bounds__(256, 2)
proj_gemm_kernel(float* __restrict__ out, const float* __restrict__ pb) {
    const __nv_bfloat16 *Ah_ = g_oAh, *Al_ = g_oAl, *Bh_ = g_wPh, *Bl_ = g_wPl;
    const int K = CC;

    extern __shared__ char smem[];
    uint32_t sbase = smem_u32(smem);
    int tid = threadIdx.x, lane = tid & 31, warp = tid >> 5;
    int m0 = blockIdx.y * 128, n0 = blockIdx.x * 128;
    int wm = (warp >> 2) * 64, wn = (warp & 3) * 32;

    int row = tid >> 1, hs = tid & 1;
    int sw = (row >> 1) & 3;
    uint32_t off0 = (uint32_t)(row * 64 + (((2*hs)   ^ sw) << 4));
    uint32_t off1 = (uint32_t)(row * 64 + (((2*hs+1) ^ sw) << 4));
    const __nv_bfloat16* gAh = Ah_ + (long)(m0 + row) * K + hs * 16;
    const __nv_bfloat16* gAl = Al_ + (long)(m0 + row) * K + hs * 16;
    const __nv_bfloat16* gBh = Bh_ + (long)(n0 + row) * K + hs * 16;
    const __nv_bfloat16* gBl = Bl_ + (long)(n0 + row) * K + hs * 16;

    float acc[4][4][4];
#pragma unroll
    for (int i = 0; i < 4; i++)
#pragma unroll
        for (int j = 0; j < 4; j++)
#pragma unroll
            for (int q = 0; q < 4; q++) acc[i][j][q] = 0.f;

    const int nch = K >> 5;
    auto issue = [&](int stage, int k0) {
        uint32_t sb = sbase + stage * GS_STAGE;
        cp16(sb + GS_AH + off0, gAh + k0);
        cp16(sb + GS_AH + off1, gAh + k0 + 8);
        cp16(sb + GS_AL + off0, gAl + k0);
        cp16(sb + GS_AL + off1, gAl + k0 + 8);
        cp16(sb + GS_BH + off0, gBh + k0);
        cp16(sb + GS_BH + off1, gBh + k0 + 8);
        cp16(sb + GS_BL + off0, gBl + k0);
        cp16(sb + GS_BL + off1, gBl + k0 + 8);
    };

    int arow_l = (lane & 15);
    int akse   = (lane >> 4);
    int brow_l = ((lane >> 4) << 3) + (lane & 7);
    int bkse   = ((lane >> 3) & 1);

    issue(0, 0);  CP_COMMIT();
    issue(1, 32); CP_COMMIT();

    for (int c = 0; c < nch; c++) {
        if (c + 2 < nch) issue((c + 2) % 3, (c + 2) * 32);
        CP_COMMIT();
        CP_WAIT2();
        __syncthreads();

        uint32_t sb = sbase + (c % 3) * GS_STAGE;
#pragma unroll
        for (int ks = 0; ks < 2; ks++) {
            uint32_t a[4][4], bh[2][4], bl[2][4];
#pragma unroll
            for (int mf = 0; mf < 4; mf++) {
                int r = wm + mf * 16 + arow_l;
                int kg = ks * 2 + akse;
                ldsm4(a[mf], sb + GS_AH + r * 64 + ((kg ^ ((r >> 1) & 3)) << 4));
            }
#pragma unroll
            for (int np = 0; np < 2; np++) {
                int r = wn + np * 16 + brow_l;
                int kg = ks * 2 + bkse;
                uint32_t ro = (uint32_t)(r * 64 + ((kg ^ ((r >> 1) & 3)) << 4));
                ldsm4(bh[np], sb + GS_BH + ro);
                ldsm4(bl[np], sb + GS_BL + ro);
            }
#pragma unroll
            for (int mf = 0; mf < 4; mf++)
#pragma unroll
                for (int nf = 0; nf < 4; nf++) {
                    int np = nf >> 1, o = (nf & 1) * 2;
                    mma16816(acc[mf][nf], a[mf][0], a[mf][1], a[mf][2], a[mf][3],
                             bh[np][o], bh[np][o + 1]);
                }
#pragma unroll
            for (int mf = 0; mf < 4; mf++)
#pragma unroll
                for (int nf = 0; nf < 4; nf++) {
                    int np = nf >> 1, o = (nf & 1) * 2;
                    mma16816(acc[mf][nf], a[mf][0], a[mf][1], a[mf][2], a[mf][3],
                             bl[np][o], bl[np][o + 1]);
                }
#pragma unroll
            for (int mf = 0; mf < 4; mf++) {
                int r = wm + mf * 16 + arow_l;
                int kg = ks * 2 + akse;
                ldsm4(a[mf], sb + GS_AL + r * 64 + ((kg ^ ((r >> 1) & 3)) << 4));
            }
#pragma unroll
            for (int mf = 0; mf < 4; mf++)
#pragma unroll
                for (int nf = 0; nf < 4; nf++) {
                    int np = nf >> 1, o = (nf & 1) * 2;
                    mma16816(acc[mf][nf], a[mf][0], a[mf][1], a[mf][2], a[mf][3],
                             bh[np][o], bh[np][o + 1]);
                }
        }
        __syncthreads();
    }

#pragma unroll
    for (int mf = 0; mf < 4; mf++) {
        int m = m0 + wm + mf * 16 + (lane >> 2);
#pragma unroll
        for (int nf = 0; nf < 4; nf++) {
            int n = n0 + wn + nf * 8 + (lane & 3) * 2;
            float2 bb = *(const float2*)&pb[n];
            *(float2*)&out[(long)m * CC + n] =
                make_float2(acc[mf][nf][0] + bb.x, acc[mf][nf][1] + bb.y);
            *(float2*)&out[(long)(m + 8) * CC + n] =
                make_float2(acc[mf][nf][2] + bb.x, acc[mf][nf][3] + bb.y);
        }
    }
}

// ============ fused flash attention (R12 version restored) ==================
// smem halves: Qh[9216] Ql[9216] | stage s: Kh[4608] Kl[4608] Vh[4608] Vl[4608]
#define FA_STAGE_H 18432
#define FA_SMEM_BYTES ((18432 + 2*FA_STAGE_H)*2)   // 110592

__global__ void __launch_bounds__(256, 2)
flash_attn_kernel(const float* __restrict__ bias,
                  const unsigned char* __restrict__ mask8,
                  float* __restrict__ attn) {
    extern __shared__ __nv_bfloat16 fsm[];
    uint32_t fb = smem_u32(fsm);

    int bh = blockIdx.y, m0 = blockIdx.x * 128;
    int b = bh >> 4, h = bh & 15;
    int tid = threadIdx.x, lane = tid & 31, w = tid >> 5;
    int g = lane >> 2, t = lane & 3;

    // producers: Q uses 2 threads/row; K/V use 4 threads/row
    int qr = tid >> 1, qsg = (tid & 1) * 4;
    int pr = tid >> 2, ps = (tid & 3) * 2;

    auto issueKV = [&](int s, int lc) {
        uint32_t sb = fb + 36864u + (uint32_t)s * (FA_STAGE_H * 2u);
        const __nv_bfloat16* kh = &g_cKh[((long)bh * LL + lc * 64 + pr) * DD + ps * 8];
        const __nv_bfloat16* kl = &g_cKl[((long)bh * LL + lc * 64 + pr) * DD + ps * 8];
#pragma unroll
        for (int i = 0; i < 2; i++) {
            cp16(sb + pr * 144 + (ps + i) * 16, kh + i * 8);
            cp16(sb + 9216u + pr * 144 + (ps + i) * 16, kl + i * 8);
        }
        const uint32_t* vh = &g_cVth[((long)bh * DD + pr) * (LL/2) + lc * 32 + ps * 4];
        const uint32_t* vl = &g_cVtl[((long)bh * DD + pr) * (LL/2) + lc * 32 + ps * 4];
#pragma unroll
        for (int i = 0; i < 2; i++) {
            cp16(sb + 18432u + pr * 144 + (ps + i) * 16, vh + i * 4);
            cp16(sb + 27648u + pr * 144 + (ps + i) * 16, vl + i * 4);
        }
    };

    {
        const __nv_bfloat16* qh = &g_cQh[((long)bh * NN + m0 + qr) * DD + qsg * 8];
        const __nv_bfloat16* ql = &g_cQl[((long)bh * NN + m0 + qr) * DD + qsg * 8];
#pragma unroll
        for (int i = 0; i < 4; i++) {
            cp16(fb + qr * 144 + (qsg + i) * 16, qh + i * 8);
            cp16(fb + 18432u + qr * 144 + (qsg + i) * 16, ql + i * 8);
        }
    }
    issueKV(0, 0);
    CP_COMMIT();

    float om0 = -1e30f, os0 = 0.f, om1 = -1e30f, os1 = 0.f;
    float acco[8][4];
#pragma unroll
    for (int i = 0; i < 8; i++)
#pragma unroll
        for (int q = 0; q < 4; q++) acco[i][q] = 0.f;

    const int arow = 16 * w + g;
    const int flag = g_maskflag;

    // ldmatrix lane-address components (same proven mapping as gemm kernels)
    const uint32_t a_r  = (uint32_t)(16 * w + (lane & 15));       // A frag row
    const uint32_t a_kg = (uint32_t)(lane >> 4);                  // A frag kseg
    const uint32_t b_r  = (uint32_t)(((lane >> 4) << 3) + (lane & 7)); // B frag row
    const uint32_t b_kg = (uint32_t)((lane >> 3) & 1);            // B frag kseg

    for (int lc = 0; lc < 16; lc++) {
        if (lc < 15) { issueKV((lc + 1) & 1, lc + 1); CP_COMMIT(); }
        if (lc < 15) { CP_WAIT1(); } else { CP_WAIT0(); }
        __syncthreads();

        uint32_t stb = fb + 36864u + (uint32_t)(lc & 1) * (FA_STAGE_H * 2u);
        uint32_t Khb = stb, Klb = stb + 9216u, Vhb = stb + 18432u, Vlb = stb + 27648u;

        float sacc[8][4];
#pragma unroll
        for (int i = 0; i < 8; i++)
#pragma unroll
            for (int q = 0; q < 4; q++) sacc[i][q] = 0.f;

#pragma unroll
        for (int ks = 0; ks < 4; ks++) {
            uint32_t aQh[4], aQl[4];
            {
                uint32_t ao = a_r * 144u + (ks * 2u + a_kg) * 16u;
                ldsm4(aQh, fb + ao);
                ldsm4(aQl, fb + 18432u + ao);
            }
            uint32_t kh[4][4], kl[4][4];
            {
                uint32_t kg = ks * 2u + b_kg;
#pragma unroll
                for (int np = 0; np < 4; np++) {
                    uint32_t ro = (np * 16u + b_r) * 144u + kg * 16u;
                    ldsm4(kh[np], Khb + ro);
                    ldsm4(kl[np], Klb + ro);
                }
            }
#pragma unroll
            for (int nf = 0; nf < 8; nf++) {
                int np = nf >> 1, o = (nf & 1) * 2;
                mma16816(sacc[nf], aQh[0], aQh[1], aQh[2], aQh[3], kh[np][o], kh[np][o+1]);
                mma16816(sacc[nf], aQl[0], aQl[1], aQl[2], aQl[3], kh[np][o], kh[np][o+1]);
            }
#pragma unroll
            for (int nf = 0; nf < 8; nf++) {
                int np = nf >> 1, o = (nf & 1) * 2;
                mma16816(sacc[nf], aQh[0], aQh[1], aQh[2], aQh[3], kl[np][o], kl[np][o+1]);
            }
        }

        // mask + bias, write attn_wo_softmax
        int r0g = m0 + arow;
        long rb0 = ((long)bh * NN + r0g) * LL + lc * 64;
        long rb1 = rb0 + 8 * LL;
        long rm0 = ((long)b * NN + r0g) * LL + lc * 64;
        long rm1 = rm0 + 8 * LL;
#pragma unroll
        for (int nf = 0; nf < 8; nf++) {
            int col = nf * 8 + 2 * t;
            float v0 = sacc[nf][0], v1 = sacc[nf][1];
            float v2 = sacc[nf][2], v3 = sacc[nf][3];
            if (flag) {
                unsigned short mA = *(const unsigned short*)&mask8[rm0 + col];
                unsigned short mB = *(const unsigned short*)&mask8[rm1 + col];
                if (mA & 0x00ff) v0 = NEGV;
                if (mA & 0xff00) v1 = NEGV;
                if (mB & 0x00ff) v2 = NEGV;
                if (mB & 0xff00) v3 = NEGV;
            } else {
                const unsigned int* m32 = (const unsigned int*)mask8;
                uint2 mA = *(const uint2*)&m32[rm0 + col];
                uint2 mB = *(const uint2*)&m32[rm1 + col];
                if (mA.x) v0 = NEGV;
                if (mA.y) v1 = NEGV;
                if (mB.x) v2 = NEGV;
                if (mB.y) v3 = NEGV;
            }
            float2 bb0 = *(const float2*)&bias[rb0 + col];
            float2 bb1 = *(const float2*)&bias[rb1 + col];
            v0 += bb0.x; v1 += bb0.y; v2 += bb1.x; v3 += bb1.y;
            *(float2*)&attn[rb0 + col] = make_float2(v0, v1);
            *(float2*)&attn[rb1 + col] = make_float2(v2, v3);
            sacc[nf][0] = v0; sacc[nf][1] = v1; sacc[nf][2] = v2; sacc[nf][3] = v3;
        }

        // online softmax (exp in place)
        float cm0 = -1e30f, cm1 = -1e30f;
#pragma unroll
        for (int nf = 0; nf < 8; nf++) {
            cm0 = fmaxf(cm0, fmaxf(sacc[nf][0], sacc[nf][1]));
            cm1 = fmaxf(cm1, fmaxf(sacc[nf][2], sacc[nf][3]));
        }
        cm0 = fmaxf(cm0, __shfl_xor_sync(0xffffffffu, cm0, 1));
        cm0 = fmaxf(cm0, __shfl_xor_sync(0xffffffffu, cm0, 2));
        cm1 = fmaxf(cm1, __shfl_xor_sync(0xffffffffu, cm1, 1));
        cm1 = fmaxf(cm1, __shfl_xor_sync(0xffffffffu, cm1, 2));
        float mn0 = fmaxf(om0, cm0), mn1 = fmaxf(om1, cm1);

        float cs0 = 0.f, cs1 = 0.f;
#pragma unroll
        for (int nf = 0; nf < 8; nf++) {
            float p0 = __expf(sacc[nf][0] - mn0);
            float p1 = __expf(sacc[nf][1] - mn0);
            float p2 = __expf(sacc[nf][2] - mn1);
            float p3 = __expf(sacc[nf][3] - mn1);
            cs0 += p0 + p1; cs1 += p2 + p3;
            sacc[nf][0] = p0; sacc[nf][1] = p1;
            sacc[nf][2] = p2; sacc[nf][3] = p3;
        }
        cs0 += __shfl_xor_sync(0xffffffffu, cs0, 1);
        cs0 += __shfl_xor_sync(0xffffffffu, cs0, 2);
        cs1 += __shfl_xor_sync(0xffffffffu, cs1, 1);
        cs1 += __shfl_xor_sync(0xffffffffu, cs1, 2);
        float f0 = __expf(om0 - mn0), f1 = __expf(om1 - mn1);
        os0 = os0 * f0 + cs0; os1 = os1 * f1 + cs1;
        om0 = mn0; om1 = mn1;

#pragma unroll
        for (int nb = 0; nb < 8; nb++) {
            acco[nb][0] *= f0; acco[nb][1] *= f0;
            acco[nb][2] *= f1; acco[nb][3] *= f1;
        }

        // O += P @ V (3-pass hi/lo), P packed on the fly, V frags via ldmatrix
#pragma unroll
        for (int ks = 0; ks < 4; ks++) {
            uint32_t vh[4][4], vl[4][4];
            {
                uint32_t kg = ks * 2u + b_kg;
#pragma unroll
                for (int np = 0; np < 4; np++) {
                    uint32_t ro = (np * 16u + b_r) * 144u + kg * 16u;
                    ldsm4(vh[np], Vhb + ro);
                    ldsm4(vl[np], Vlb + ro);
                }
            }
            float e0, e1, e2, e3, e4, e5, e6, e7;
            uint32_t pa0 = pack2bf(sacc[2*ks][0],   sacc[2*ks][1],   e0, e1);
            uint32_t pa1 = pack2bf(sacc[2*ks][2],   sacc[2*ks][3],   e2, e3);
            uint32_t pa2 = pack2bf(sacc[2*ks+1][0], sacc[2*ks+1][1], e4, e5);
            uint32_t pa3 = pack2bf(sacc[2*ks+1][2], sacc[2*ks+1][3], e6, e7);
            uint32_t qa0 = pack2bf_only(e0, e1);
            uint32_t qa1 = pack2bf_only(e2, e3);
            uint32_t qa2 = pack2bf_only(e4, e5);
            uint32_t qa3 = pack2bf_only(e6, e7);
#pragma unroll
            for (int nb = 0; nb < 8; nb++) {
                int np = nb >> 1, o = (nb & 1) * 2;
                mma16816(acco[nb], pa0, pa1, pa2, pa3, vh[np][o], vh[np][o+1]);
                mma16816(acco[nb], qa0, qa1, qa2, qa3, vh[np][o], vh[np][o+1]);
            }
#pragma unroll
            for (int nb = 0; nb < 8; nb++) {
                int np = nb >> 1, o = (nb & 1) * 2;
                mma16816(acco[nb], pa0, pa1, pa2, pa3, vl[np][o], vl[np][o+1]);
            }
        }
        __syncthreads();
    }

    // O epilogue: write packed bf16 hi/lo directly (layout = proj A operand)
    float rv0 = 1.0f / os0, rv1 = 1.0f / os1;
    int r0g = m0 + arow;
    uint32_t* oh = (uint32_t*)g_oAh;
    uint32_t* ol = (uint32_t*)g_oAl;
    long ob0w = (((long)b * NN + r0g) * CC + h * 64) >> 1;
    long ob1w = (((long)b * NN + r0g + 8) * CC + h * 64) >> 1;
#pragma unroll
    for (int nb = 0; nb < 8; nb++) {
        int dw = nb * 4 + t;
        float r0, r1;
        uint32_t hi0 = pack2bf(acco[nb][0] * rv0, acco[nb][1] * rv0, r0, r1);
        oh[ob0w + dw] = hi0;
        ol[ob0w + dw] = pack2bf_only(r0, r1);
        uint32_t hi1 = pack2bf(acco[nb][2] * rv1, acco[nb][3] * rv1, r0, r1);
        oh[ob1w + dw] = hi1;
        ol[ob1w + dw] = pack2bf_only(r0, r1);
    }
}

// ---------------- launch --------------------------------------------------
extern "C" void kernel_launch(void* const* d_in, const int* in_sizes, int n_in,
                              void* d_out, int out_size) {
    const float* query  = (const float*)d_in[0];
    const float* memory = (const float*)d_in[1];
    const float* bias   = (const float*)d_in[2];
    const unsigned char* mask = (const unsigned char*)d_in[3];
    const float* q_w    = (const float*)d_in[4];
    const float* kv_w   = (const float*)d_in[5];
    const float* proj_w = (const float*)d_in[6];
    const float* proj_b = (const float*)d_in[7];

    float* x_out    = (float*)d_out;
    float* attn_out = x_out + (long)BB * NN * CC;   // x first, then attn_wo_softmax

    (void)in_sizes; (void)n_in; (void)out_size;

    static int inited = 0;
    if (!inited) {
        cudaFuncSetAttribute(qkv_gemm_kernel,  cudaFuncAttributeMaxDynamicSharedMemorySize, G_SMEM_BYTES);
        cudaFuncSetAttribute(proj_gemm_kernel, cudaFuncAttributeMaxDynamicSharedMemorySize, G_SMEM_BYTES);
        cudaFuncSetAttribute(flash_attn_kernel, cudaFuncAttributeMaxDynamicSharedMemorySize, FA_SMEM_BYTES);
        inited = 1;
    }

    // all input conversions + mask detection in one launch (block 6144 = detect)
    conv_pre_kernel<<<6145, 256>>>(query, memory, q_w, kv_w, proj_w, mask);

    // Q + KV projections, flattened grid (no dead CTAs)
    qkv_gemm_kernel<<<dim3(24, 32), 256, G_SMEM_BYTES>>>();

    // V transpose to pair-packed bf16 hi/lo
    convVt_kernel<<<dim3(LL/64, BH), 256>>>();

    // fused attention: S (+mask+bias) -> attn_out, online softmax, packed O
    flash_attn_kernel<<<dim3(NN/128, BH), 256, FA_SMEM_BYTES>>>(bias, mask, attn_out);

    // output projection
    proj_gemm_kernel<<<dim3(CC/128, (BB*NN)/128), 256, G_SMEM_BYTES>>>(x_out, proj_b);
}

// round 15
// speedup vs baseline: 1.3497x; 1.3070x over previous
#include <cuda_runtime.h>
#include <cuda_fp16.h>
#include <math.h>
#include <stdint.h>

// Problem dims
#define BB 4
#define NN 1024
#define LL 1024
#define CC 1024
#define HH 16
#define DD 64
#define BH (BB*HH)          // 64
#define SCALE 0.125f        // D^-0.5
#define NEGV (-65504.0f)

// ---------------- scratch (device globals; no allocations allowed) ----------
__device__ float g_V[BB*HH*LL*DD];   // (B,H,L,D) fp32 (for V transpose)
__device__ int   g_maskflag;

// fp16 hi/lo buffers (B-side operands are hi-only under the 2-pass scheme)
__device__ __half g_qAh[BB*NN*CC], g_qAl[BB*NN*CC];      // query conv (A: hi/lo)
__device__ __half g_mAh[BB*LL*CC], g_mAl[BB*LL*CC];      // memory conv (A: hi/lo)
__device__ __half g_wQh[CC*CC];                          // q_w (B: hi)
__device__ __half g_wKVh[2*CC*CC];                       // kv_w (B: hi)
__device__ __half g_wPh[CC*CC];                          // proj_w (B: hi)
__device__ __half g_oAh[BB*NN*CC], g_oAl[BB*NN*CC];      // O packed (A for proj)
__device__ __half g_cQh[BB*HH*NN*DD], g_cQl[BB*HH*NN*DD]; // Q scaled (A: hi/lo)
__device__ __half g_cKh[BB*HH*LL*DD];                     // K (B: hi)
__device__ uint32_t g_cVth[BB*HH*DD*LL/2];                // V^T hi pair-packed

// ============================ helpers ========================================
__device__ __forceinline__ uint32_t smem_u32(const void* p) {
    uint32_t a;
    asm("{ .reg .u64 t; cvta.to.shared.u64 t, %1; cvt.u32.u64 %0, t; }" : "=r"(a) : "l"(p));
    return a;
}

__device__ __forceinline__ void cvt8h(float4 x, float4 y, float s, uint4& h, uint4& l) {
    float a[8] = {x.x*s, x.y*s, x.z*s, x.w*s, y.x*s, y.y*s, y.z*s, y.w*s};
    unsigned int hh[4], ll[4];
#pragma unroll
    for (int i = 0; i < 4; i++) {
        __half h0 = __float2half(a[2*i]);
        __half h1 = __float2half(a[2*i+1]);
        float r0 = a[2*i]   - __half2float(h0);
        float r1 = a[2*i+1] - __half2float(h1);
        __half l0 = __float2half(r0);
        __half l1 = __float2half(r1);
        hh[i] = (unsigned)__half_as_ushort(h0) | ((unsigned)__half_as_ushort(h1) << 16);
        ll[i] = (unsigned)__half_as_ushort(l0) | ((unsigned)__half_as_ushort(l1) << 16);
    }
    h = make_uint4(hh[0], hh[1], hh[2], hh[3]);
    l = make_uint4(ll[0], ll[1], ll[2], ll[3]);
}

__device__ __forceinline__ uint32_t pack2h(float x0, float x1, float& r0, float& r1) {
    __half h0 = __float2half(x0);
    __half h1 = __float2half(x1);
    r0 = x0 - __half2float(h0);
    r1 = x1 - __half2float(h1);
    return (unsigned)__half_as_ushort(h0) | ((unsigned)__half_as_ushort(h1) << 16);
}
__device__ __forceinline__ uint32_t pack2h_only(float x0, float x1) {
    __half h0 = __float2half(x0);
    __half h1 = __float2half(x1);
    return (unsigned)__half_as_ushort(h0) | ((unsigned)__half_as_ushort(h1) << 16);
}

__device__ __forceinline__ void mma16816(float* c, uint32_t a0, uint32_t a1,
                                         uint32_t a2, uint32_t a3,
                                         uint32_t b0, uint32_t b1) {
    asm volatile(
        "mma.sync.aligned.m16n8k16.row.col.f32.f16.f16.f32 "
        "{%0,%1,%2,%3}, {%4,%5,%6,%7}, {%8,%9}, {%0,%1,%2,%3};"
        : "+f"(c[0]), "+f"(c[1]), "+f"(c[2]), "+f"(c[3])
        : "r"(a0), "r"(a1), "r"(a2), "r"(a3), "r"(b0), "r"(b1));
}

__device__ __forceinline__ void ldsm4(uint32_t* r, uint32_t addr) {
    asm volatile("ldmatrix.sync.aligned.m8n8.x4.shared.b16 {%0,%1,%2,%3}, [%4];"
        : "=r"(r[0]), "=r"(r[1]), "=r"(r[2]), "=r"(r[3]) : "r"(addr));
}

__device__ __forceinline__ void cp16(uint32_t saddr, const void* g) {
    asm volatile("cp.async.cg.shared.global [%0], [%1], 16;" :: "r"(saddr), "l"(g));
}
#define CP_COMMIT() asm volatile("cp.async.commit_group;" ::: "memory")
#define CP_WAIT2()  asm volatile("cp.async.wait_group 2;" ::: "memory")
#define CP_WAIT1()  asm volatile("cp.async.wait_group 1;" ::: "memory")
#define CP_WAIT0()  asm volatile("cp.async.wait_group 0;" ::: "memory")

// ------- all-input fp32 -> fp16 hi/lo conversion + mask detect (one launch) -
__global__ void __launch_bounds__(256)
conv_pre_kernel(const float* __restrict__ q, const float* __restrict__ m,
                const float* __restrict__ qw, const float* __restrict__ kvw,
                const float* __restrict__ pw, const unsigned char* __restrict__ mk) {
    if (blockIdx.x == 6144) {
        __shared__ int s;
        if (threadIdx.x == 0) s = 0;
        __syncthreads();
        int found = 0;
        for (int j = threadIdx.x; j < 16384; j += 256)
            if (mk[4*j + 1]) found = 1;
        if (found) atomicOr(&s, 1);
        __syncthreads();
        if (threadIdx.x == 0) g_maskflag = s;
        return;
    }
    int i = blockIdx.x * 256 + threadIdx.x;
    const float* src; uint4* oh; uint4* ol; int j; int wantl;
    if (i < 524288)       { src = q;   oh = (uint4*)g_qAh;  ol = (uint4*)g_qAl; j = i;            wantl = 1; }
    else if (i < 1048576) { src = m;   oh = (uint4*)g_mAh;  ol = (uint4*)g_mAl; j = i - 524288;   wantl = 1; }
    else if (i < 1179648) { src = qw;  oh = (uint4*)g_wQh;  ol = 0;             j = i - 1048576;  wantl = 0; }
    else if (i < 1441792) { src = kvw; oh = (uint4*)g_wKVh; ol = 0;             j = i - 1179648;  wantl = 0; }
    else                  { src = pw;  oh = (uint4*)g_wPh;  ol = 0;             j = i - 1441792;  wantl = 0; }
    float4 a = ((const float4*)src)[2*j];
    float4 b = ((const float4*)src)[2*j + 1];
    uint4 h, l;
    cvt8h(a, b, 1.0f, h, l);
    oh[j] = h;
    if (wantl) ol[j] = l;
}

// ---------------- V transpose + hi pack: g_V -> g_cVth ----------------------
__global__ void __launch_bounds__(256)
convVt_kernel() {
    __shared__ float tile[64][65];
    int bh = blockIdx.y, l0 = blockIdx.x * 64;
    int tid = threadIdx.x;
    const float* Vp = g_V + ((long)bh * LL + l0) * DD;
#pragma unroll
    for (int i = 0; i < 16; i++) {
        int idx = tid + 256 * i;
        int r = idx >> 6, d = idx & 63;
        tile[r][d] = Vp[(long)r * DD + d];
    }
    __syncthreads();
#pragma unroll
    for (int i = 0; i < 8; i++) {
        int w = tid + 256 * i;
        int d = w >> 5, j = w & 31;
        float v0 = tile[2*j][d], v1 = tile[2*j+1][d];
        long o = ((long)bh * DD + d) * (LL/2) + (l0 >> 1) + j;
        g_cVth[o] = pack2h_only(v0, v1);
    }
}

// ====== pipelined fp16 GEMM core (2-pass: Ah*Bh + Al*Bh) ====================
#define GS_AH 0
#define GS_AL 8192
#define GS_BH 16384
#define GS_STAGE 24576
#define G_SMEM_BYTES (3 * GS_STAGE)   // 73728

// combined Q + KV projection, flattened grid: x<8 -> Q tile x, else KV tile x-8
__global__ void __launch_bounds__(256, 2)
qkv_gemm_kernel() {
    int bx = blockIdx.x;
    int z = (bx < 8) ? 0 : 1;
    int nx = (bx < 8) ? bx : (bx - 8);
    const __half *Ah_, *Al_, *Bh_;
    if (z == 0) { Ah_ = g_qAh; Al_ = g_qAl; Bh_ = g_wQh;  }
    else        { Ah_ = g_mAh; Al_ = g_mAl; Bh_ = g_wKVh; }
    const int K = CC;

    extern __shared__ char smem[];
    uint32_t sbase = smem_u32(smem);
    int tid = threadIdx.x, lane = tid & 31, warp = tid >> 5;
    int m0 = blockIdx.y * 128, n0 = nx * 128;
    int wm = (warp >> 2) * 64, wn = (warp & 3) * 32;

    int row = tid >> 1, hs = tid & 1;
    int sw = (row >> 1) & 3;
    uint32_t off0 = (uint32_t)(row * 64 + (((2*hs)   ^ sw) << 4));
    uint32_t off1 = (uint32_t)(row * 64 + (((2*hs+1) ^ sw) << 4));
    const __half* gAh = Ah_ + (long)(m0 + row) * K + hs * 16;
    const __half* gAl = Al_ + (long)(m0 + row) * K + hs * 16;
    const __half* gBh = Bh_ + (long)(n0 + row) * K + hs * 16;

    float acc[4][4][4];
#pragma unroll
    for (int i = 0; i < 4; i++)
#pragma unroll
        for (int j = 0; j < 4; j++)
#pragma unroll
            for (int q = 0; q < 4; q++) acc[i][j][q] = 0.f;

    const int nch = K >> 5;
    auto issue = [&](int stage, int k0) {
        uint32_t sb = sbase + stage * GS_STAGE;
        cp16(sb + GS_AH + off0, gAh + k0);
        cp16(sb + GS_AH + off1, gAh + k0 + 8);
        cp16(sb + GS_AL + off0, gAl + k0);
        cp16(sb + GS_AL + off1, gAl + k0 + 8);
        cp16(sb + GS_BH + off0, gBh + k0);
        cp16(sb + GS_BH + off1, gBh + k0 + 8);
    };

    int arow_l = (lane & 15);
    int akse   = (lane >> 4);
    int brow_l = ((lane >> 4) << 3) + (lane & 7);
    int bkse   = ((lane >> 3) & 1);

    issue(0, 0);  CP_COMMIT();
    issue(1, 32); CP_COMMIT();

    for (int c = 0; c < nch; c++) {
        if (c + 2 < nch) issue((c + 2) % 3, (c + 2) * 32);
        CP_COMMIT();
        CP_WAIT2();
        __syncthreads();

        uint32_t sb = sbase + (c % 3) * GS_STAGE;
#pragma unroll
        for (int ks = 0; ks < 2; ks++) {
            uint32_t a[4][4], bh[2][4];
#pragma unroll
            for (int mf = 0; mf < 4; mf++) {
                int r = wm + mf * 16 + arow_l;
                int kg = ks * 2 + akse;
                ldsm4(a[mf], sb + GS_AH + r * 64 + ((kg ^ ((r >> 1) & 3)) << 4));
            }
#pragma unroll
            for (int np = 0; np < 2; np++) {
                int r = wn + np * 16 + brow_l;
                int kg = ks * 2 + bkse;
                uint32_t ro = (uint32_t)(r * 64 + ((kg ^ ((r >> 1) & 3)) << 4));
                ldsm4(bh[np], sb + GS_BH + ro);
            }
#pragma unroll
            for (int mf = 0; mf < 4; mf++)
#pragma unroll
                for (int nf = 0; nf < 4; nf++) {
                    int np = nf >> 1, o = (nf & 1) * 2;
                    mma16816(acc[mf][nf], a[mf][0], a[mf][1], a[mf][2], a[mf][3],
                             bh[np][o], bh[np][o + 1]);
                }
#pragma unroll
            for (int mf = 0; mf < 4; mf++) {
                int r = wm + mf * 16 + arow_l;
                int kg = ks * 2 + akse;
                ldsm4(a[mf], sb + GS_AL + r * 64 + ((kg ^ ((r >> 1) & 3)) << 4));
            }
#pragma unroll
            for (int mf = 0; mf < 4; mf++)
#pragma unroll
                for (int nf = 0; nf < 4; nf++) {
                    int np = nf >> 1, o = (nf & 1) * 2;
                    mma16816(acc[mf][nf], a[mf][0], a[mf][1], a[mf][2], a[mf][3],
                             bh[np][o], bh[np][o + 1]);
                }
        }
        __syncthreads();
    }

#pragma unroll
    for (int mf = 0; mf < 4; mf++) {
        int m = m0 + wm + mf * 16 + (lane >> 2);
#pragma unroll
        for (int nf = 0; nf < 4; nf++) {
            int n = n0 + wn + nf * 8 + (lane & 3) * 2;
#pragma unroll
            for (int half = 0; half < 2; half++) {
                int mm = m + half * 8;
                float v0 = acc[mf][nf][2*half], v1 = acc[mf][nf][2*half + 1];
                int b = mm >> 10, rr = mm & 1023;
                if (z == 0) {
                    int hh = n >> 6, d = n & 63;
                    long e = (((long)(b << 4) + hh) * NN + rr) * DD + d;
                    float r0, r1;
                    uint32_t hi = pack2h(v0 * SCALE, v1 * SCALE, r0, r1);
                    *(uint32_t*)&g_cQh[e] = hi;
                    *(uint32_t*)&g_cQl[e] = pack2h_only(r0, r1);
                } else if (n < CC) {
                    int hh = n >> 6, d = n & 63;
                    long e = (((long)(b << 4) + hh) * LL + rr) * DD + d;
                    *(uint32_t*)&g_cKh[e] = pack2h_only(v0, v1);
                } else {
                    int cc = n - CC, hh = cc >> 6, d = cc & 63;
                    *(float2*)&g_V[(((b << 4) + hh) * LL + rr) * DD + d] = make_float2(v0, v1);
                }
            }
        }
    }
}

// ---------------- output projection GEMM (reads packed O) -------------------
__global__ void __launch_bounds__(256, 2)
proj_gemm_kernel(float* __restrict__ out, const float* __restrict__ pb) {
    const __half *Ah_ = g_oAh, *Al_ = g_oAl, *Bh_ = g_wPh;
    const int K = CC;

    extern __shared__ char smem[];
    uint32_t sbase = smem_u32(smem);
    int tid = threadIdx.x, lane = tid & 31, warp = tid >> 5;
    int m0 = blockIdx.y * 128, n0 = blockIdx.x * 128;
    int wm = (warp >> 2) * 64, wn = (warp & 3) * 32;

    int row = tid >> 1, hs = tid & 1;
    int sw = (row >> 1) & 3;
    uint32_t off0 = (uint32_t)(row * 64 + (((2*hs)   ^ sw) << 4));
    uint32_t off1 = (uint32_t)(row * 64 + (((2*hs+1) ^ sw) << 4));
    const __half* gAh = Ah_ + (long)(m0 + row) * K + hs * 16;
    const __half* gAl = Al_ + (long)(m0 + row) * K + hs * 16;
    const __half* gBh = Bh_ + (long)(n0 + row) * K + hs * 16;

    float acc[4][4][4];
#pragma unroll
    for (int i = 0; i < 4; i++)
#pragma unroll
        for (int j = 0; j < 4; j++)
#pragma unroll
            for (int q = 0; q < 4; q++) acc[i][j][q] = 0.f;

    const int nch = K >> 5;
    auto issue = [&](int stage, int k0) {
        uint32_t sb = sbase + stage * GS_STAGE;
        cp16(sb + GS_AH + off0, gAh + k0);
        cp16(sb + GS_AH + off1, gAh + k0 + 8);
        cp16(sb + GS_AL + off0, gAl + k0);
        cp16(sb + GS_AL + off1, gAl + k0 + 8);
        cp16(sb + GS_BH + off0, gBh + k0);
        cp16(sb + GS_BH + off1, gBh + k0 + 8);
    };

    int arow_l = (lane & 15);
    int akse   = (lane >> 4);
    int brow_l = ((lane >> 4) << 3) + (lane & 7);
    int bkse   = ((lane >> 3) & 1);

    issue(0, 0);  CP_COMMIT();
    issue(1, 32); CP_COMMIT();

    for (int c = 0; c < nch; c++) {
        if (c + 2 < nch) issue((c + 2) % 3, (c + 2) * 32);
        CP_COMMIT();
        CP_WAIT2();
        __syncthreads();

        uint32_t sb = sbase + (c % 3) * GS_STAGE;
#pragma unroll
        for (int ks = 0; ks < 2; ks++) {
            uint32_t a[4][4], bh[2][4];
#pragma unroll
            for (int mf = 0; mf < 4; mf++) {
                int r = wm + mf * 16 + arow_l;
                int kg = ks * 2 + akse;
                ldsm4(a[mf], sb + GS_AH + r * 64 + ((kg ^ ((r >> 1) & 3)) << 4));
            }
#pragma unroll
            for (int np = 0; np < 2; np++) {
                int r = wn + np * 16 + brow_l;
                int kg = ks * 2 + bkse;
                uint32_t ro = (uint32_t)(r * 64 + ((kg ^ ((r >> 1) & 3)) << 4));
                ldsm4(bh[np], sb + GS_BH + ro);
            }
#pragma unroll
            for (int mf = 0; mf < 4; mf++)
#pragma unroll
                for (int nf = 0; nf < 4; nf++) {
                    int np = nf >> 1, o = (nf & 1) * 2;
                    mma16816(acc[mf][nf], a[mf][0], a[mf][1], a[mf][2], a[mf][3],
                             bh[np][o], bh[np][o + 1]);
                }
#pragma unroll
            for (int mf = 0; mf < 4; mf++) {
                int r = wm + mf * 16 + arow_l;
                int kg = ks * 2 + akse;
                ldsm4(a[mf], sb + GS_AL + r * 64 + ((kg ^ ((r >> 1) & 3)) << 4));
            }
#pragma unroll
            for (int mf = 0; mf < 4; mf++)
#pragma unroll
                for (int nf = 0; nf < 4; nf++) {
                    int np = nf >> 1, o = (nf & 1) * 2;
                    mma16816(acc[mf][nf], a[mf][0], a[mf][1], a[mf][2], a[mf][3],
                             bh[np][o], bh[np][o + 1]);
                }
        }
        __syncthreads();
    }

#pragma unroll
    for (int mf = 0; mf < 4; mf++) {
        int m = m0 + wm + mf * 16 + (lane >> 2);
#pragma unroll
        for (int nf = 0; nf < 4; nf++) {
            int n = n0 + wn + nf * 8 + (lane & 3) * 2;
            float2 bb = *(const float2*)&pb[n];
            *(float2*)&out[(long)m * CC + n] =
                make_float2(acc[mf][nf][0] + bb.x, acc[mf][nf][1] + bb.y);
            *(float2*)&out[(long)(m + 8) * CC + n] =
                make_float2(acc[mf][nf][2] + bb.x, acc[mf][nf][3] + bb.y);
        }
    }
}

// ============ fused flash attention (fp16 2-pass; R12 pipeline) =============
// smem halves layout (bytes): Qh[18432] Ql[18432] | stage s: Kh[9216] Vh[9216]
#define FA_STAGE_B 18432u
#define FA_SMEM_BYTES (36864 + 2*18432)   // 73728

__global__ void __launch_bounds__(256, 2)
flash_attn_kernel(const float* __restrict__ bias,
                  const unsigned char* __restrict__ mask8,
                  float* __restrict__ attn) {
    extern __shared__ __half fsm[];
    uint32_t fb = smem_u32(fsm);

    int bh = blockIdx.y, m0 = blockIdx.x * 128;
    int b = bh >> 4, h = bh & 15;
    int tid = threadIdx.x, lane = tid & 31, w = tid >> 5;
    int g = lane >> 2, t = lane & 3;

    // producers: Q uses 2 threads/row; K/V use 4 threads/row
    int qr = tid >> 1, qsg = (tid & 1) * 4;
    int pr = tid >> 2, ps = (tid & 3) * 2;

    auto issueKV = [&](int s, int lc) {
        uint32_t sb = fb + 36864u + (uint32_t)s * FA_STAGE_B;
        const __half* kh = &g_cKh[((long)bh * LL + lc * 64 + pr) * DD + ps * 8];
#pragma unroll
        for (int i = 0; i < 2; i++)
            cp16(sb + pr * 144 + (ps + i) * 16, kh + i * 8);
        const uint32_t* vh = &g_cVth[((long)bh * DD + pr) * (LL/2) + lc * 32 + ps * 4];
#pragma unroll
        for (int i = 0; i < 2; i++)
            cp16(sb + 9216u + pr * 144 + (ps + i) * 16, vh + i * 4);
    };

    {
        const __half* qh = &g_cQh[((long)bh * NN + m0 + qr) * DD + qsg * 8];
        const __half* ql = &g_cQl[((long)bh * NN + m0 + qr) * DD + qsg * 8];
#pragma unroll
        for (int i = 0; i < 4; i++) {
            cp16(fb + qr * 144 + (qsg + i) * 16, qh + i * 8);
            cp16(fb + 18432u + qr * 144 + (qsg + i) * 16, ql + i * 8);
        }
    }
    issueKV(0, 0);
    CP_COMMIT();

    float om0 = -1e30f, os0 = 0.f, om1 = -1e30f, os1 = 0.f;
    float acco[8][4];
#pragma unroll
    for (int i = 0; i < 8; i++)
#pragma unroll
        for (int q = 0; q < 4; q++) acco[i][q] = 0.f;

    const int arow = 16 * w + g;
    const int flag = g_maskflag;

    const uint32_t a_r  = (uint32_t)(16 * w + (lane & 15));
    const uint32_t a_kg = (uint32_t)(lane >> 4);
    const uint32_t b_r  = (uint32_t)(((lane >> 4) << 3) + (lane & 7));
    const uint32_t b_kg = (uint32_t)((lane >> 3) & 1);

    for (int lc = 0; lc < 16; lc++) {
        if (lc < 15) { issueKV((lc + 1) & 1, lc + 1); CP_COMMIT(); }
        if (lc < 15) { CP_WAIT1(); } else { CP_WAIT0(); }
        __syncthreads();

        uint32_t stb = fb + 36864u + (uint32_t)(lc & 1) * FA_STAGE_B;
        uint32_t Khb = stb, Vhb = stb + 9216u;

        float sacc[8][4];
#pragma unroll
        for (int i = 0; i < 8; i++)
#pragma unroll
            for (int q = 0; q < 4; q++) sacc[i][q] = 0.f;

#pragma unroll
        for (int ks = 0; ks < 4; ks++) {
            uint32_t aQh[4], aQl[4];
            {
                uint32_t ao = a_r * 144u + (ks * 2u + a_kg) * 16u;
                ldsm4(aQh, fb + ao);
                ldsm4(aQl, fb + 18432u + ao);
            }
            uint32_t kh[4][4];
            {
                uint32_t kg = ks * 2u + b_kg;
#pragma unroll
                for (int np = 0; np < 4; np++) {
                    uint32_t ro = (np * 16u + b_r) * 144u + kg * 16u;
                    ldsm4(kh[np], Khb + ro);
                }
            }
#pragma unroll
            for (int nf = 0; nf < 8; nf++) {
                int np = nf >> 1, o = (nf & 1) * 2;
                mma16816(sacc[nf], aQh[0], aQh[1], aQh[2], aQh[3], kh[np][o], kh[np][o+1]);
            }
#pragma unroll
            for (int nf = 0; nf < 8; nf++) {
                int np = nf >> 1, o = (nf & 1) * 2;
                mma16816(sacc[nf], aQl[0], aQl[1], aQl[2], aQl[3], kh[np][o], kh[np][o+1]);
            }
        }

        // mask + bias, write attn_wo_softmax
        int r0g = m0 + arow;
        long rb0 = ((long)bh * NN + r0g) * LL + lc * 64;
        long rb1 = rb0 + 8 * LL;
        long rm0 = ((long)b * NN + r0g) * LL + lc * 64;
        long rm1 = rm0 + 8 * LL;
#pragma unroll
        for (int nf = 0; nf < 8; nf++) {
            int col = nf * 8 + 2 * t;
            float v0 = sacc[nf][0], v1 = sacc[nf][1];
            float v2 = sacc[nf][2], v3 = sacc[nf][3];
            if (flag) {
                unsigned short mA = *(const unsigned short*)&mask8[rm0 + col];
                unsigned short mB = *(const unsigned short*)&mask8[rm1 + col];
                if (mA & 0x00ff) v0 = NEGV;
                if (mA & 0xff00) v1 = NEGV;
                if (mB & 0x00ff) v2 = NEGV;
                if (mB & 0xff00) v3 = NEGV;
            } else {
                const unsigned int* m32 = (const unsigned int*)mask8;
                uint2 mA = *(const uint2*)&m32[rm0 + col];
                uint2 mB = *(const uint2*)&m32[rm1 + col];
                if (mA.x) v0 = NEGV;
                if (mA.y) v1 = NEGV;
                if (mB.x) v2 = NEGV;
                if (mB.y) v3 = NEGV;
            }
            float2 bb0 = *(const float2*)&bias[rb0 + col];
            float2 bb1 = *(const float2*)&bias[rb1 + col];
            v0 += bb0.x; v1 += bb0.y; v2 += bb1.x; v3 += bb1.y;
            *(float2*)&attn[rb0 + col] = make_float2(v0, v1);
            *(float2*)&attn[rb1 + col] = make_float2(v2, v3);
            sacc[nf][0] = v0; sacc[nf][1] = v1; sacc[nf][2] = v2; sacc[nf][3] = v3;
        }

        // online softmax (exp in place)
        float cm0 = -1e30f, cm1 = -1e30f;
#pragma unroll
        for (int nf = 0; nf < 8; nf++) {
            cm0 = fmaxf(cm0, fmaxf(sacc[nf][0], sacc[nf][1]));
            cm1 = fmaxf(cm1, fmaxf(sacc[nf][2], sacc[nf][3]));
        }
        cm0 = fmaxf(cm0, __shfl_xor_sync(0xffffffffu, cm0, 1));
        cm0 = fmaxf(cm0, __shfl_xor_sync(0xffffffffu, cm0, 2));
        cm1 = fmaxf(cm1, __shfl_xor_sync(0xffffffffu, cm1, 1));
        cm1 = fmaxf(cm1, __shfl_xor_sync(0xffffffffu, cm1, 2));
        float mn0 = fmaxf(om0, cm0), mn1 = fmaxf(om1, cm1);

        float cs0 = 0.f, cs1 = 0.f;
#pragma unroll
        for (int nf = 0; nf < 8; nf++) {
            float p0 = __expf(sacc[nf][0] - mn0);
            float p1 = __expf(sacc[nf][1] - mn0);
            float p2 = __expf(sacc[nf][2] - mn1);
            float p3 = __expf(sacc[nf][3] - mn1);
            cs0 += p0 + p1; cs1 += p2 + p3;
            sacc[nf][0] = p0; sacc[nf][1] = p1;
            sacc[nf][2] = p2; sacc[nf][3] = p3;
        }
        cs0 += __shfl_xor_sync(0xffffffffu, cs0, 1);
        cs0 += __shfl_xor_sync(0xffffffffu, cs0, 2);
        cs1 += __shfl_xor_sync(0xffffffffu, cs1, 1);
        cs1 += __shfl_xor_sync(0xffffffffu, cs1, 2);
        float f0 = __expf(om0 - mn0), f1 = __expf(om1 - mn1);
        os0 = os0 * f0 + cs0; os1 = os1 * f1 + cs1;
        om0 = mn0; om1 = mn1;

#pragma unroll
        for (int nb = 0; nb < 8; nb++) {
            acco[nb][0] *= f0; acco[nb][1] *= f0;
            acco[nb][2] *= f1; acco[nb][3] *= f1;
        }

        // O += P @ V (2-pass hi/lo), P packed on the fly, V frags via ldmatrix
#pragma unroll
        for (int ks = 0; ks < 4; ks++) {
            uint32_t vh[4][4];
            {
                uint32_t kg = ks * 2u + b_kg;
#pragma unroll
                for (int np = 0; np < 4; np++) {
                    uint32_t ro = (np * 16u + b_r) * 144u + kg * 16u;
                    ldsm4(vh[np], Vhb + ro);
                }
            }
            float e0, e1, e2, e3, e4, e5, e6, e7;
            uint32_t pa0 = pack2h(sacc[2*ks][0],   sacc[2*ks][1],   e0, e1);
            uint32_t pa1 = pack2h(sacc[2*ks][2],   sacc[2*ks][3],   e2, e3);
            uint32_t pa2 = pack2h(sacc[2*ks+1][0], sacc[2*ks+1][1], e4, e5);
            uint32_t pa3 = pack2h(sacc[2*ks+1][2], sacc[2*ks+1][3], e6, e7);
            uint32_t qa0 = pack2h_only(e0, e1);
            uint32_t qa1 = pack2h_only(e2, e3);
            uint32_t qa2 = pack2h_only(e4, e5);
            uint32_t qa3 = pack2h_only(e6, e7);
#pragma unroll
            for (int nb = 0; nb < 8; nb++) {
                int np = nb >> 1, o = (nb & 1) * 2;
                mma16816(acco[nb], pa0, pa1, pa2, pa3, vh[np][o], vh[np][o+1]);
            }
#pragma unroll
            for (int nb = 0; nb < 8; nb++) {
                int np = nb >> 1, o = (nb & 1) * 2;
                mma16816(acco[nb], qa0, qa1, qa2, qa3, vh[np][o], vh[np][o+1]);
            }
        }
        __syncthreads();
    }

    // O epilogue: write packed fp16 hi/lo directly (layout = proj A operand)
    float rv0 = 1.0f / os0, rv1 = 1.0f / os1;
    int r0g = m0 + arow;
    uint32_t* oh = (uint32_t*)g_oAh;
    uint32_t* ol = (uint32_t*)g_oAl;
    long ob0w = (((long)b * NN + r0g) * CC + h * 64) >> 1;
    long ob1w = (((long)b * NN + r0g + 8) * CC + h * 64) >> 1;
#pragma unroll
    for (int nb = 0; nb < 8; nb++) {
        int dw = nb * 4 + t;
        float r0, r1;
        uint32_t hi0 = pack2h(acco[nb][0] * rv0, acco[nb][1] * rv0, r0, r1);
        oh[ob0w + dw] = hi0;
        ol[ob0w + dw] = pack2h_only(r0, r1);
        uint32_t hi1 = pack2h(acco[nb][2] * rv1, acco[nb][3] * rv1, r0, r1);
        oh[ob1w + dw] = hi1;
        ol[ob1w + dw] = pack2h_only(r0, r1);
    }
}

// ---------------- launch --------------------------------------------------
extern "C" void kernel_launch(void* const* d_in, const int* in_sizes, int n_in,
                              void* d_out, int out_size) {
    const float* query  = (const float*)d_in[0];
    const float* memory = (const float*)d_in[1];
    const float* bias   = (const float*)d_in[2];
    const unsigned char* mask = (const unsigned char*)d_in[3];
    const float* q_w    = (const float*)d_in[4];
    const float* kv_w   = (const float*)d_in[5];
    const float* proj_w = (const float*)d_in[6];
    const float* proj_b = (const float*)d_in[7];

    float* x_out    = (float*)d_out;
    float* attn_out = x_out + (long)BB * NN * CC;   // x first, then attn_wo_softmax

    (void)in_sizes; (void)n_in; (void)out_size;

    static int inited = 0;
    if (!inited) {
        cudaFuncSetAttribute(qkv_gemm_kernel,  cudaFuncAttributeMaxDynamicSharedMemorySize, G_SMEM_BYTES);
        cudaFuncSetAttribute(proj_gemm_kernel, cudaFuncAttributeMaxDynamicSharedMemorySize, G_SMEM_BYTES);
        cudaFuncSetAttribute(flash_attn_kernel, cudaFuncAttributeMaxDynamicSharedMemorySize, FA_SMEM_BYTES);
        inited = 1;
    }

    // all input conversions + mask detection in one launch (block 6144 = detect)
    conv_pre_kernel<<<6145, 256>>>(query, memory, q_w, kv_w, proj_w, mask);

    // Q + KV projections, flattened grid (no dead CTAs)
    qkv_gemm_kernel<<<dim3(24, 32), 256, G_SMEM_BYTES>>>();

    // V transpose to pair-packed fp16 hi
    convVt_kernel<<<dim3(LL/64, BH), 256>>>();

    // fused attention: S (+mask+bias) -> attn_out, online softmax, packed O
    flash_attn_kernel<<<dim3(NN/128, BH), 256, FA_SMEM_BYTES>>>(bias, mask, attn_out);

    // output projection
    proj_gemm_kernel<<<dim3(CC/128, (BB*NN)/128), 256, G_SMEM_BYTES>>>(x_out, proj_b);
}

// round 16
// speedup vs baseline: 1.4058x; 1.0416x over previous
#include <cuda_runtime.h>
#include <cuda_fp16.h>
#include <math.h>
#include <stdint.h>

// Problem dims
#define BB 4
#define NN 1024
#define LL 1024
#define CC 1024
#define HH 16
#define DD 64
#define BH (BB*HH)          // 64
#define SCALE 0.125f        // D^-0.5
#define NEGV (-65504.0f)

// ---------------- scratch (device globals; no allocations allowed) ----------
__device__ float g_V[BB*HH*LL*DD];   // (B,H,L,D) fp32 (for V transpose)
__device__ int   g_maskflag;

// fp16 hi/lo buffers (B-side operands are hi-only under the 2-pass scheme)
__device__ __half g_qAh[BB*NN*CC], g_qAl[BB*NN*CC];      // query conv (A: hi/lo)
__device__ __half g_mAh[BB*LL*CC], g_mAl[BB*LL*CC];      // memory conv (A: hi/lo)
__device__ __half g_wQh[CC*CC];                          // q_w (B: hi)
__device__ __half g_wKVh[2*CC*CC];                       // kv_w (B: hi)
__device__ __half g_wPh[CC*CC];                          // proj_w (B: hi)
__device__ __half g_oAh[BB*NN*CC], g_oAl[BB*NN*CC];      // O packed (A for proj)
__device__ __half g_cQh[BB*HH*NN*DD], g_cQl[BB*HH*NN*DD]; // Q scaled (A: hi/lo)
__device__ __half g_cKh[BB*HH*LL*DD];                     // K (B: hi)
__device__ uint32_t g_cVth[BB*HH*DD*LL/2];                // V^T hi pair-packed

// ============================ helpers ========================================
__device__ __forceinline__ uint32_t smem_u32(const void* p) {
    uint32_t a;
    asm("{ .reg .u64 t; cvta.to.shared.u64 t, %1; cvt.u32.u64 %0, t; }" : "=r"(a) : "l"(p));
    return a;
}

__device__ __forceinline__ void cvt8h(float4 x, float4 y, float s, uint4& h, uint4& l) {
    float a[8] = {x.x*s, x.y*s, x.z*s, x.w*s, y.x*s, y.y*s, y.z*s, y.w*s};
    unsigned int hh[4], ll[4];
#pragma unroll
    for (int i = 0; i < 4; i++) {
        __half h0 = __float2half(a[2*i]);
        __half h1 = __float2half(a[2*i+1]);
        float r0 = a[2*i]   - __half2float(h0);
        float r1 = a[2*i+1] - __half2float(h1);
        __half l0 = __float2half(r0);
        __half l1 = __float2half(r1);
        hh[i] = (unsigned)__half_as_ushort(h0) | ((unsigned)__half_as_ushort(h1) << 16);
        ll[i] = (unsigned)__half_as_ushort(l0) | ((unsigned)__half_as_ushort(l1) << 16);
    }
    h = make_uint4(hh[0], hh[1], hh[2], hh[3]);
    l = make_uint4(ll[0], ll[1], ll[2], ll[3]);
}

__device__ __forceinline__ uint32_t pack2h(float x0, float x1, float& r0, float& r1) {
    __half h0 = __float2half(x0);
    __half h1 = __float2half(x1);
    r0 = x0 - __half2float(h0);
    r1 = x1 - __half2float(h1);
    return (unsigned)__half_as_ushort(h0) | ((unsigned)__half_as_ushort(h1) << 16);
}
__device__ __forceinline__ uint32_t pack2h_only(float x0, float x1) {
    __half h0 = __float2half(x0);
    __half h1 = __float2half(x1);
    return (unsigned)__half_as_ushort(h0) | ((unsigned)__half_as_ushort(h1) << 16);
}

__device__ __forceinline__ void mma16816(float* c, uint32_t a0, uint32_t a1,
                                         uint32_t a2, uint32_t a3,
                                         uint32_t b0, uint32_t b1) {
    asm volatile(
        "mma.sync.aligned.m16n8k16.row.col.f32.f16.f16.f32 "
        "{%0,%1,%2,%3}, {%4,%5,%6,%7}, {%8,%9}, {%0,%1,%2,%3};"
        : "+f"(c[0]), "+f"(c[1]), "+f"(c[2]), "+f"(c[3])
        : "r"(a0), "r"(a1), "r"(a2), "r"(a3), "r"(b0), "r"(b1));
}

__device__ __forceinline__ void ldsm4(uint32_t* r, uint32_t addr) {
    asm volatile("ldmatrix.sync.aligned.m8n8.x4.shared.b16 {%0,%1,%2,%3}, [%4];"
        : "=r"(r[0]), "=r"(r[1]), "=r"(r[2]), "=r"(r[3]) : "r"(addr));
}

__device__ __forceinline__ void cp16(uint32_t saddr, const void* g) {
    asm volatile("cp.async.cg.shared.global [%0], [%1], 16;" :: "r"(saddr), "l"(g));
}
#define CP_COMMIT() asm volatile("cp.async.commit_group;" ::: "memory")
#define CP_WAIT3()  asm volatile("cp.async.wait_group 3;" ::: "memory")
#define CP_WAIT2()  asm volatile("cp.async.wait_group 2;" ::: "memory")
#define CP_WAIT0()  asm volatile("cp.async.wait_group 0;" ::: "memory")

// ------- all-input fp32 -> fp16 hi/lo conversion + mask detect (one launch) -
__global__ void __launch_bounds__(256)
conv_pre_kernel(const float* __restrict__ q, const float* __restrict__ m,
                const float* __restrict__ qw, const float* __restrict__ kvw,
                const float* __restrict__ pw, const unsigned char* __restrict__ mk) {
    if (blockIdx.x == 6144) {
        __shared__ int s;
        if (threadIdx.x == 0) s = 0;
        __syncthreads();
        int found = 0;
        for (int j = threadIdx.x; j < 16384; j += 256)
            if (mk[4*j + 1]) found = 1;
        if (found) atomicOr(&s, 1);
        __syncthreads();
        if (threadIdx.x == 0) g_maskflag = s;
        return;
    }
    int i = blockIdx.x * 256 + threadIdx.x;
    const float* src; uint4* oh; uint4* ol; int j; int wantl;
    if (i < 524288)       { src = q;   oh = (uint4*)g_qAh;  ol = (uint4*)g_qAl; j = i;            wantl = 1; }
    else if (i < 1048576) { src = m;   oh = (uint4*)g_mAh;  ol = (uint4*)g_mAl; j = i - 524288;   wantl = 1; }
    else if (i < 1179648) { src = qw;  oh = (uint4*)g_wQh;  ol = 0;             j = i - 1048576;  wantl = 0; }
    else if (i < 1441792) { src = kvw; oh = (uint4*)g_wKVh; ol = 0;             j = i - 1179648;  wantl = 0; }
    else                  { src = pw;  oh = (uint4*)g_wPh;  ol = 0;             j = i - 1441792;  wantl = 0; }
    float4 a = ((const float4*)src)[2*j];
    float4 b = ((const float4*)src)[2*j + 1];
    uint4 h, l;
    cvt8h(a, b, 1.0f, h, l);
    oh[j] = h;
    if (wantl) ol[j] = l;
}

// ---------------- V transpose + hi pack: g_V -> g_cVth ----------------------
__global__ void __launch_bounds__(256)
convVt_kernel() {
    __shared__ float tile[64][65];
    int bh = blockIdx.y, l0 = blockIdx.x * 64;
    int tid = threadIdx.x;
    const float* Vp = g_V + ((long)bh * LL + l0) * DD;
#pragma unroll
    for (int i = 0; i < 16; i++) {
        int idx = tid + 256 * i;
        int r = idx >> 6, d = idx & 63;
        tile[r][d] = Vp[(long)r * DD + d];
    }
    __syncthreads();
#pragma unroll
    for (int i = 0; i < 8; i++) {
        int w = tid + 256 * i;
        int d = w >> 5, j = w & 31;
        float v0 = tile[2*j][d], v1 = tile[2*j+1][d];
        long o = ((long)bh * DD + d) * (LL/2) + (l0 >> 1) + j;
        g_cVth[o] = pack2h_only(v0, v1);
    }
}

// ====== pipelined fp16 GEMM core (2-pass: Ah*Bh + Al*Bh; 4 stages) ==========
#define GS_AH 0
#define GS_AL 8192
#define GS_BH 16384
#define GS_STAGE 24576
#define G_SMEM_BYTES (4 * GS_STAGE)   // 98304

// combined Q + KV projection, flattened grid: x<8 -> Q tile x, else KV tile x-8
__global__ void __launch_bounds__(256, 2)
qkv_gemm_kernel() {
    int bx = blockIdx.x;
    int z = (bx < 8) ? 0 : 1;
    int nx = (bx < 8) ? bx : (bx - 8);
    const __half *Ah_, *Al_, *Bh_;
    if (z == 0) { Ah_ = g_qAh; Al_ = g_qAl; Bh_ = g_wQh;  }
    else        { Ah_ = g_mAh; Al_ = g_mAl; Bh_ = g_wKVh; }
    const int K = CC;

    extern __shared__ char smem[];
    uint32_t sbase = smem_u32(smem);
    int tid = threadIdx.x, lane = tid & 31, warp = tid >> 5;
    int m0 = blockIdx.y * 128, n0 = nx * 128;
    int wm = (warp >> 2) * 64, wn = (warp & 3) * 32;

    int row = tid >> 1, hs = tid & 1;
    int sw = (row >> 1) & 3;
    uint32_t off0 = (uint32_t)(row * 64 + (((2*hs)   ^ sw) << 4));
    uint32_t off1 = (uint32_t)(row * 64 + (((2*hs+1) ^ sw) << 4));
    const __half* gAh = Ah_ + (long)(m0 + row) * K + hs * 16;
    const __half* gAl = Al_ + (long)(m0 + row) * K + hs * 16;
    const __half* gBh = Bh_ + (long)(n0 + row) * K + hs * 16;

    float acc[4][4][4];
#pragma unroll
    for (int i = 0; i < 4; i++)
#pragma unroll
        for (int j = 0; j < 4; j++)
#pragma unroll
            for (int q = 0; q < 4; q++) acc[i][j][q] = 0.f;

    const int nch = K >> 5;
    auto issue = [&](int stage, int k0) {
        uint32_t sb = sbase + stage * GS_STAGE;
        cp16(sb + GS_AH + off0, gAh + k0);
        cp16(sb + GS_AH + off1, gAh + k0 + 8);
        cp16(sb + GS_AL + off0, gAl + k0);
        cp16(sb + GS_AL + off1, gAl + k0 + 8);
        cp16(sb + GS_BH + off0, gBh + k0);
        cp16(sb + GS_BH + off1, gBh + k0 + 8);
    };

    int arow_l = (lane & 15);
    int akse   = (lane >> 4);
    int brow_l = ((lane >> 4) << 3) + (lane & 7);
    int bkse   = ((lane >> 3) & 1);

    issue(0, 0);  CP_COMMIT();
    issue(1, 32); CP_COMMIT();
    issue(2, 64); CP_COMMIT();

    for (int c = 0; c < nch; c++) {
        if (c + 3 < nch) issue((c + 3) & 3, (c + 3) * 32);
        CP_COMMIT();
        CP_WAIT3();
        __syncthreads();

        uint32_t sb = sbase + (c & 3) * GS_STAGE;
#pragma unroll
        for (int ks = 0; ks < 2; ks++) {
            uint32_t a[4][4], bh[2][4];
#pragma unroll
            for (int mf = 0; mf < 4; mf++) {
                int r = wm + mf * 16 + arow_l;
                int kg = ks * 2 + akse;
                ldsm4(a[mf], sb + GS_AH + r * 64 + ((kg ^ ((r >> 1) & 3)) << 4));
            }
#pragma unroll
            for (int np = 0; np < 2; np++) {
                int r = wn + np * 16 + brow_l;
                int kg = ks * 2 + bkse;
                uint32_t ro = (uint32_t)(r * 64 + ((kg ^ ((r >> 1) & 3)) << 4));
                ldsm4(bh[np], sb + GS_BH + ro);
            }
#pragma unroll
            for (int mf = 0; mf < 4; mf++)
#pragma unroll
                for (int nf = 0; nf < 4; nf++) {
                    int np = nf >> 1, o = (nf & 1) * 2;
                    mma16816(acc[mf][nf], a[mf][0], a[mf][1], a[mf][2], a[mf][3],
                             bh[np][o], bh[np][o + 1]);
                }
#pragma unroll
            for (int mf = 0; mf < 4; mf++) {
                int r = wm + mf * 16 + arow_l;
                int kg = ks * 2 + akse;
                ldsm4(a[mf], sb + GS_AL + r * 64 + ((kg ^ ((r >> 1) & 3)) << 4));
            }
#pragma unroll
            for (int mf = 0; mf < 4; mf++)
#pragma unroll
                for (int nf = 0; nf < 4; nf++) {
                    int np = nf >> 1, o = (nf & 1) * 2;
                    mma16816(acc[mf][nf], a[mf][0], a[mf][1], a[mf][2], a[mf][3],
                             bh[np][o], bh[np][o + 1]);
                }
        }
        __syncthreads();
    }

#pragma unroll
    for (int mf = 0; mf < 4; mf++) {
        int m = m0 + wm + mf * 16 + (lane >> 2);
#pragma unroll
        for (int nf = 0; nf < 4; nf++) {
            int n = n0 + wn + nf * 8 + (lane & 3) * 2;
#pragma unroll
            for (int half = 0; half < 2; half++) {
                int mm = m + half * 8;
                float v0 = acc[mf][nf][2*half], v1 = acc[mf][nf][2*half + 1];
                int b = mm >> 10, rr = mm & 1023;
                if (z == 0) {
                    int hh = n >> 6, d = n & 63;
                    long e = (((long)(b << 4) + hh) * NN + rr) * DD + d;
                    float r0, r1;
                    uint32_t hi = pack2h(v0 * SCALE, v1 * SCALE, r0, r1);
                    *(uint32_t*)&g_cQh[e] = hi;
                    *(uint32_t*)&g_cQl[e] = pack2h_only(r0, r1);
                } else if (n < CC) {
                    int hh = n >> 6, d = n & 63;
                    long e = (((long)(b << 4) + hh) * LL + rr) * DD + d;
                    *(uint32_t*)&g_cKh[e] = pack2h_only(v0, v1);
                } else {
                    int cc = n - CC, hh = cc >> 6, d = cc & 63;
                    *(float2*)&g_V[(((b << 4) + hh) * LL + rr) * DD + d] = make_float2(v0, v1);
                }
            }
        }
    }
}

// ---------------- output projection GEMM (reads packed O; 4 stages) ---------
__global__ void __launch_bounds__(256, 2)
proj_gemm_kernel(float* __restrict__ out, const float* __restrict__ pb) {
    const __half *Ah_ = g_oAh, *Al_ = g_oAl, *Bh_ = g_wPh;
    const int K = CC;

    extern __shared__ char smem[];
    uint32_t sbase = smem_u32(smem);
    int tid = threadIdx.x, lane = tid & 31, warp = tid >> 5;
    int m0 = blockIdx.y * 128, n0 = blockIdx.x * 128;
    int wm = (warp >> 2) * 64, wn = (warp & 3) * 32;

    int row = tid >> 1, hs = tid & 1;
    int sw = (row >> 1) & 3;
    uint32_t off0 = (uint32_t)(row * 64 + (((2*hs)   ^ sw) << 4));
    uint32_t off1 = (uint32_t)(row * 64 + (((2*hs+1) ^ sw) << 4));
    const __half* gAh = Ah_ + (long)(m0 + row) * K + hs * 16;
    const __half* gAl = Al_ + (long)(m0 + row) * K + hs * 16;
    const __half* gBh = Bh_ + (long)(n0 + row) * K + hs * 16;

    float acc[4][4][4];
#pragma unroll
    for (int i = 0; i < 4; i++)
#pragma unroll
        for (int j = 0; j < 4; j++)
#pragma unroll
            for (int q = 0; q < 4; q++) acc[i][j][q] = 0.f;

    const int nch = K >> 5;
    auto issue = [&](int stage, int k0) {
        uint32_t sb = sbase + stage * GS_STAGE;
        cp16(sb + GS_AH + off0, gAh + k0);
        cp16(sb + GS_AH + off1, gAh + k0 + 8);
        cp16(sb + GS_AL + off0, gAl + k0);
        cp16(sb + GS_AL + off1, gAl + k0 + 8);
        cp16(sb + GS_BH + off0, gBh + k0);
        cp16(sb + GS_BH + off1, gBh + k0 + 8);
    };

    int arow_l = (lane & 15);
    int akse   = (lane >> 4);
    int brow_l = ((lane >> 4) << 3) + (lane & 7);
    int bkse   = ((lane >> 3) & 1);

    issue(0, 0);  CP_COMMIT();
    issue(1, 32); CP_COMMIT();
    issue(2, 64); CP_COMMIT();

    for (int c = 0; c < nch; c++) {
        if (c + 3 < nch) issue((c + 3) & 3, (c + 3) * 32);
        CP_COMMIT();
        CP_WAIT3();
        __syncthreads();

        uint32_t sb = sbase + (c & 3) * GS_STAGE;
#pragma unroll
        for (int ks = 0; ks < 2; ks++) {
            uint32_t a[4][4], bh[2][4];
#pragma unroll
            for (int mf = 0; mf < 4; mf++) {
                int r = wm + mf * 16 + arow_l;
                int kg = ks * 2 + akse;
                ldsm4(a[mf], sb + GS_AH + r * 64 + ((kg ^ ((r >> 1) & 3)) << 4));
            }
#pragma unroll
            for (int np = 0; np < 2; np++) {
                int r = wn + np * 16 + brow_l;
                int kg = ks * 2 + bkse;
                uint32_t ro = (uint32_t)(r * 64 + ((kg ^ ((r >> 1) & 3)) << 4));
                ldsm4(bh[np], sb + GS_BH + ro);
            }
#pragma unroll
            for (int mf = 0; mf < 4; mf++)
#pragma unroll
                for (int nf = 0; nf < 4; nf++) {
                    int np = nf >> 1, o = (nf & 1) * 2;
                    mma16816(acc[mf][nf], a[mf][0], a[mf][1], a[mf][2], a[mf][3],
                             bh[np][o], bh[np][o + 1]);
                }
#pragma unroll
            for (int mf = 0; mf < 4; mf++) {
                int r = wm + mf * 16 + arow_l;
                int kg = ks * 2 + akse;
                ldsm4(a[mf], sb + GS_AL + r * 64 + ((kg ^ ((r >> 1) & 3)) << 4));
            }
#pragma unroll
            for (int mf = 0; mf < 4; mf++)
#pragma unroll
                for (int nf = 0; nf < 4; nf++) {
                    int np = nf >> 1, o = (nf & 1) * 2;
                    mma16816(acc[mf][nf], a[mf][0], a[mf][1], a[mf][2], a[mf][3],
                             bh[np][o], bh[np][o + 1]);
                }
        }
        __syncthreads();
    }

#pragma unroll
    for (int mf = 0; mf < 4; mf++) {
        int m = m0 + wm + mf * 16 + (lane >> 2);
#pragma unroll
        for (int nf = 0; nf < 4; nf++) {
            int n = n0 + wn + nf * 8 + (lane & 3) * 2;
            float2 bb = *(const float2*)&pb[n];
            *(float2*)&out[(long)m * CC + n] =
                make_float2(acc[mf][nf][0] + bb.x, acc[mf][nf][1] + bb.y);
            *(float2*)&out[(long)(m + 8) * CC + n] =
                make_float2(acc[mf][nf][2] + bb.x, acc[mf][nf][3] + bb.y);
        }
    }
}

// ============ fused flash attention (fp16 2-pass; 3-stage KV pipeline) ======
// smem layout (bytes): Qh[18432] Ql[18432] | stage s in {0,1,2}: Kh[9216] Vh[9216]
#define FA_STAGE_B 18432u
#define FA_SMEM_BYTES (36864 + 3*18432)   // 92160

__global__ void __launch_bounds__(256, 2)
flash_attn_kernel(const float* __restrict__ bias,
                  const unsigned char* __restrict__ mask8,
                  float* __restrict__ attn) {
    extern __shared__ __half fsm[];
    uint32_t fb = smem_u32(fsm);

    int bh = blockIdx.y, m0 = blockIdx.x * 128;
    int b = bh >> 4, h = bh & 15;
    int tid = threadIdx.x, lane = tid & 31, w = tid >> 5;
    int g = lane >> 2, t = lane & 3;

    // producers: Q uses 2 threads/row; K/V use 4 threads/row
    int qr = tid >> 1, qsg = (tid & 1) * 4;
    int pr = tid >> 2, ps = (tid & 3) * 2;

    auto issueKV = [&](int s, int lc) {
        uint32_t sb = fb + 36864u + (uint32_t)s * FA_STAGE_B;
        const __half* kh = &g_cKh[((long)bh * LL + lc * 64 + pr) * DD + ps * 8];
#pragma unroll
        for (int i = 0; i < 2; i++)
            cp16(sb + pr * 144 + (ps + i) * 16, kh + i * 8);
        const uint32_t* vh = &g_cVth[((long)bh * DD + pr) * (LL/2) + lc * 32 + ps * 4];
#pragma unroll
        for (int i = 0; i < 2; i++)
            cp16(sb + 9216u + pr * 144 + (ps + i) * 16, vh + i * 4);
    };

    {
        const __half* qh = &g_cQh[((long)bh * NN + m0 + qr) * DD + qsg * 8];
        const __half* ql = &g_cQl[((long)bh * NN + m0 + qr) * DD + qsg * 8];
#pragma unroll
        for (int i = 0; i < 4; i++) {
            cp16(fb + qr * 144 + (qsg + i) * 16, qh + i * 8);
            cp16(fb + 18432u + qr * 144 + (qsg + i) * 16, ql + i * 8);
        }
    }
    issueKV(0, 0);
    CP_COMMIT();
    issueKV(1, 1);
    CP_COMMIT();

    float om0 = -1e30f, os0 = 0.f, om1 = -1e30f, os1 = 0.f;
    float acco[8][4];
#pragma unroll
    for (int i = 0; i < 8; i++)
#pragma unroll
        for (int q = 0; q < 4; q++) acco[i][q] = 0.f;

    const int arow = 16 * w + g;
    const int flag = g_maskflag;

    const uint32_t a_r  = (uint32_t)(16 * w + (lane & 15));
    const uint32_t a_kg = (uint32_t)(lane >> 4);
    const uint32_t b_r  = (uint32_t)(((lane >> 4) << 3) + (lane & 7));
    const uint32_t b_kg = (uint32_t)((lane >> 3) & 1);

    for (int lc = 0; lc < 16; lc++) {
        if (lc + 2 < 16) issueKV((lc + 2) % 3, lc + 2);
        CP_COMMIT();
        CP_WAIT2();
        __syncthreads();

        uint32_t stb = fb + 36864u + (uint32_t)(lc % 3) * FA_STAGE_B;
        uint32_t Khb = stb, Vhb = stb + 9216u;

        float sacc[8][4];
#pragma unroll
        for (int i = 0; i < 8; i++)
#pragma unroll
            for (int q = 0; q < 4; q++) sacc[i][q] = 0.f;

#pragma unroll
        for (int ks = 0; ks < 4; ks++) {
            uint32_t aQh[4], aQl[4];
            {
                uint32_t ao = a_r * 144u + (ks * 2u + a_kg) * 16u;
                ldsm4(aQh, fb + ao);
                ldsm4(aQl, fb + 18432u + ao);
            }
            uint32_t kh[4][4];
            {
                uint32_t kg = ks * 2u + b_kg;
#pragma unroll
                for (int np = 0; np < 4; np++) {
                    uint32_t ro = (np * 16u + b_r) * 144u + kg * 16u;
                    ldsm4(kh[np], Khb + ro);
                }
            }
#pragma unroll
            for (int nf = 0; nf < 8; nf++) {
                int np = nf >> 1, o = (nf & 1) * 2;
                mma16816(sacc[nf], aQh[0], aQh[1], aQh[2], aQh[3], kh[np][o], kh[np][o+1]);
            }
#pragma unroll
            for (int nf = 0; nf < 8; nf++) {
                int np = nf >> 1, o = (nf & 1) * 2;
                mma16816(sacc[nf], aQl[0], aQl[1], aQl[2], aQl[3], kh[np][o], kh[np][o+1]);
            }
        }

        // mask + bias, write attn_wo_softmax
        int r0g = m0 + arow;
        long rb0 = ((long)bh * NN + r0g) * LL + lc * 64;
        long rb1 = rb0 + 8 * LL;
        long rm0 = ((long)b * NN + r0g) * LL + lc * 64;
        long rm1 = rm0 + 8 * LL;
#pragma unroll
        for (int nf = 0; nf < 8; nf++) {
            int col = nf * 8 + 2 * t;
            float v0 = sacc[nf][0], v1 = sacc[nf][1];
            float v2 = sacc[nf][2], v3 = sacc[nf][3];
            if (flag) {
                unsigned short mA = *(const unsigned short*)&mask8[rm0 + col];
                unsigned short mB = *(const unsigned short*)&mask8[rm1 + col];
                if (mA & 0x00ff) v0 = NEGV;
                if (mA & 0xff00) v1 = NEGV;
                if (mB & 0x00ff) v2 = NEGV;
                if (mB & 0xff00) v3 = NEGV;
            } else {
                const unsigned int* m32 = (const unsigned int*)mask8;
                uint2 mA = *(const uint2*)&m32[rm0 + col];
                uint2 mB = *(const uint2*)&m32[rm1 + col];
                if (mA.x) v0 = NEGV;
                if (mA.y) v1 = NEGV;
                if (mB.x) v2 = NEGV;
                if (mB.y) v3 = NEGV;
            }
            float2 bb0 = *(const float2*)&bias[rb0 + col];
            float2 bb1 = *(const float2*)&bias[rb1 + col];
            v0 += bb0.x; v1 += bb0.y; v2 += bb1.x; v3 += bb1.y;
            *(float2*)&attn[rb0 + col] = make_float2(v0, v1);
            *(float2*)&attn[rb1 + col] = make_float2(v2, v3);
            sacc[nf][0] = v0; sacc[nf][1] = v1; sacc[nf][2] = v2; sacc[nf][3] = v3;
        }

        // online softmax (exp in place)
        float cm0 = -1e30f, cm1 = -1e30f;
#pragma unroll
        for (int nf = 0; nf < 8; nf++) {
            cm0 = fmaxf(cm0, fmaxf(sacc[nf][0], sacc[nf][1]));
            cm1 = fmaxf(cm1, fmaxf(sacc[nf][2], sacc[nf][3]));
        }
        cm0 = fmaxf(cm0, __shfl_xor_sync(0xffffffffu, cm0, 1));
        cm0 = fmaxf(cm0, __shfl_xor_sync(0xffffffffu, cm0, 2));
        cm1 = fmaxf(cm1, __shfl_xor_sync(0xffffffffu, cm1, 1));
        cm1 = fmaxf(cm1, __shfl_xor_sync(0xffffffffu, cm1, 2));
        float mn0 = fmaxf(om0, cm0), mn1 = fmaxf(om1, cm1);

        float cs0 = 0.f, cs1 = 0.f;
#pragma unroll
        for (int nf = 0; nf < 8; nf++) {
            float p0 = __expf(sacc[nf][0] - mn0);
            float p1 = __expf(sacc[nf][1] - mn0);
            float p2 = __expf(sacc[nf][2] - mn1);
            float p3 = __expf(sacc[nf][3] - mn1);
            cs0 += p0 + p1; cs1 += p2 + p3;
            sacc[nf][0] = p0; sacc[nf][1] = p1;
            sacc[nf][2] = p2; sacc[nf][3] = p3;
        }
        cs0 += __shfl_xor_sync(0xffffffffu, cs0, 1);
        cs0 += __shfl_xor_sync(0xffffffffu, cs0, 2);
        cs1 += __shfl_xor_sync(0xffffffffu, cs1, 1);
        cs1 += __shfl_xor_sync(0xffffffffu, cs1, 2);
        float f0 = __expf(om0 - mn0), f1 = __expf(om1 - mn1);
        os0 = os0 * f0 + cs0; os1 = os1 * f1 + cs1;
        om0 = mn0; om1 = mn1;

#pragma unroll
        for (int nb = 0; nb < 8; nb++) {
            acco[nb][0] *= f0; acco[nb][1] *= f0;
            acco[nb][2] *= f1; acco[nb][3] *= f1;
        }

        // O += P @ V (2-pass hi/lo), P packed on the fly, V frags via ldmatrix
#pragma unroll
        for (int ks = 0; ks < 4; ks++) {
            uint32_t vh[4][4];
            {
                uint32_t kg = ks * 2u + b_kg;
#pragma unroll
                for (int np = 0; np < 4; np++) {
                    uint32_t ro = (np * 16u + b_r) * 144u + kg * 16u;
                    ldsm4(vh[np], Vhb + ro);
                }
            }
            float e0, e1, e2, e3, e4, e5, e6, e7;
            uint32_t pa0 = pack2h(sacc[2*ks][0],   sacc[2*ks][1],   e0, e1);
            uint32_t pa1 = pack2h(sacc[2*ks][2],   sacc[2*ks][3],   e2, e3);
            uint32_t pa2 = pack2h(sacc[2*ks+1][0], sacc[2*ks+1][1], e4, e5);
            uint32_t pa3 = pack2h(sacc[2*ks+1][2], sacc[2*ks+1][3], e6, e7);
            uint32_t qa0 = pack2h_only(e0, e1);
            uint32_t qa1 = pack2h_only(e2, e3);
            uint32_t qa2 = pack2h_only(e4, e5);
            uint32_t qa3 = pack2h_only(e6, e7);
#pragma unroll
            for (int nb = 0; nb < 8; nb++) {
                int np = nb >> 1, o = (nb & 1) * 2;
                mma16816(acco[nb], pa0, pa1, pa2, pa3, vh[np][o], vh[np][o+1]);
            }
#pragma unroll
            for (int nb = 0; nb < 8; nb++) {
                int np = nb >> 1, o = (nb & 1) * 2;
                mma16816(acco[nb], qa0, qa1, qa2, qa3, vh[np][o], vh[np][o+1]);
            }
        }
        __syncthreads();
    }

    // O epilogue: write packed fp16 hi/lo directly (layout = proj A operand)
    float rv0 = 1.0f / os0, rv1 = 1.0f / os1;
    int r0g = m0 + arow;
    uint32_t* oh = (uint32_t*)g_oAh;
    uint32_t* ol = (uint32_t*)g_oAl;
    long ob0w = (((long)b * NN + r0g) * CC + h * 64) >> 1;
    long ob1w = (((long)b * NN + r0g + 8) * CC + h * 64) >> 1;
#pragma unroll
    for (int nb = 0; nb < 8; nb++) {
        int dw = nb * 4 + t;
        float r0, r1;
        uint32_t hi0 = pack2h(acco[nb][0] * rv0, acco[nb][1] * rv0, r0, r1);
        oh[ob0w + dw] = hi0;
        ol[ob0w + dw] = pack2h_only(r0, r1);
        uint32_t hi1 = pack2h(acco[nb][2] * rv1, acco[nb][3] * rv1, r0, r1);
        oh[ob1w + dw] = hi1;
        ol[ob1w + dw] = pack2h_only(r0, r1);
    }
}

// ---------------- launch --------------------------------------------------
extern "C" void kernel_launch(void* const* d_in, const int* in_sizes, int n_in,
                              void* d_out, int out_size) {
    const float* query  = (const float*)d_in[0];
    const float* memory = (const float*)d_in[1];
    const float* bias   = (const float*)d_in[2];
    const unsigned char* mask = (const unsigned char*)d_in[3];
    const float* q_w    = (const float*)d_in[4];
    const float* kv_w   = (const float*)d_in[5];
    const float* proj_w = (const float*)d_in[6];
    const float* proj_b = (const float*)d_in[7];

    float* x_out    = (float*)d_out;
    float* attn_out = x_out + (long)BB * NN * CC;   // x first, then attn_wo_softmax

    (void)in_sizes; (void)n_in; (void)out_size;

    static int inited = 0;
    if (!inited) {
        cudaFuncSetAttribute(qkv_gemm_kernel,  cudaFuncAttributeMaxDynamicSharedMemorySize, G_SMEM_BYTES);
        cudaFuncSetAttribute(proj_gemm_kernel, cudaFuncAttributeMaxDynamicSharedMemorySize, G_SMEM_BYTES);
        cudaFuncSetAttribute(flash_attn_kernel, cudaFuncAttributeMaxDynamicSharedMemorySize, FA_SMEM_BYTES);
        inited = 1;
    }

    // all input conversions + mask detection in one launch (block 6144 = detect)
    conv_pre_kernel<<<6145, 256>>>(query, memory, q_w, kv_w, proj_w, mask);

    // Q + KV projections, flattened grid (no dead CTAs)
    qkv_gemm_kernel<<<dim3(24, 32), 256, G_SMEM_BYTES>>>();

    // V transpose to pair-packed fp16 hi
    convVt_kernel<<<dim3(LL/64, BH), 256>>>();

    // fused attention: S (+mask+bias) -> attn_out, online softmax, packed O
    flash_attn_kernel<<<dim3(NN/128, BH), 256, FA_SMEM_BYTES>>>(bias, mask, attn_out);

    // output projection
    proj_gemm_kernel<<<dim3(CC/128, (BB*NN)/128), 256, G_SMEM_BYTES>>>(x_out, proj_b);
}